// round 7
// baseline (speedup 1.0000x reference)
#include <cuda_runtime.h>
#include <math.h>
#include <stdint.h>

// ---------------- problem constants ----------------
#define BB 4
#define NN 1024
#define CC 768
#define HH 12
#define TWO_D 128
#define MROWS (BB*NN)    // 4096
#define SCALE 0.125f     // D^-0.5
#define EPS 1e-5f
#define OUT_SCALE 0.8f   // 1 - LAMBDA_INIT

// ---------------- scratch (device globals; no alloc allowed) ----------------
__device__ float g_xn  [MROWS*CC];
__device__ float g_q   [MROWS*2*CC];
__device__ float g_k   [MROWS*2*CC];
__device__ float g_v   [MROWS*2*CC];
__device__ float g_o1  [MROWS*2*CC];
__device__ float g_o2  [MROWS*2*CC];
__device__ float g_att [MROWS*2*CC];
__device__ float g_xmid[MROWS*CC];
__device__ float g_xn2 [MROWS*CC];
__device__ float g_h   [MROWS*4*CC];

// ================= helpers =================
__device__ __forceinline__ uint32_t f2tf32(float f) {
    uint32_t r;
    asm("cvt.rna.tf32.f32 %0, %1;" : "=r"(r) : "f"(f));
    return r;
}
__device__ __forceinline__ void mma_tf32(float* c, const uint32_t* a, const uint32_t* b) {
    asm volatile("mma.sync.aligned.m16n8k8.row.col.f32.tf32.tf32.f32 "
        "{%0,%1,%2,%3}, {%4,%5,%6,%7}, {%8,%9}, {%0,%1,%2,%3};"
        : "+f"(c[0]), "+f"(c[1]), "+f"(c[2]), "+f"(c[3])
        : "r"(a[0]), "r"(a[1]), "r"(a[2]), "r"(a[3]), "r"(b[0]), "r"(b[1]));
}

// ================= LayerNorm over 768 =================
__global__ __launch_bounds__(256) void ln_kernel(
    const float* __restrict__ x, const float* __restrict__ w,
    const float* __restrict__ b, float* __restrict__ out)
{
    int row = blockIdx.x;
    int tid = threadIdx.x;
    const float* xr = x + (size_t)row * CC;
    float v0 = xr[tid], v1 = xr[tid + 256], v2 = xr[tid + 512];
    float s  = v0 + v1 + v2;
    float sq = v0*v0 + v1*v1 + v2*v2;
#pragma unroll
    for (int off = 16; off >= 1; off >>= 1) {
        s  += __shfl_xor_sync(0xffffffffu, s,  off);
        sq += __shfl_xor_sync(0xffffffffu, sq, off);
    }
    __shared__ float rs_[8], rq_[8];
    __shared__ float smu, srs;
    int wid = tid >> 5, lane = tid & 31;
    if (lane == 0) { rs_[wid] = s; rq_[wid] = sq; }
    __syncthreads();
    if (tid == 0) {
        float S = 0.f, Q = 0.f;
#pragma unroll
        for (int i = 0; i < 8; i++) { S += rs_[i]; Q += rq_[i]; }
        float mu = S / (float)CC;
        float var = Q / (float)CC - mu * mu;
        smu = mu; srs = rsqrtf(var + EPS);
    }
    __syncthreads();
    float mu = smu, r = srs;
    float* orow = out + (size_t)row * CC;
    orow[tid]       = (v0 - mu) * r * w[tid]       + b[tid];
    orow[tid + 256] = (v1 - mu) * r * w[tid + 256] + b[tid + 256];
    orow[tid + 512] = (v2 - mu) * r * w[tid + 512] + b[tid + 512];
}

// ================= TF32 mma.sync GEMM: C = A(MxK) * B(NxK)^T =================
// Round-5 proven structure: 128x128 tile, 8 warps (2m x 4n), 64x32 warp tile,
// double-buffered smem, register prefetch of next chunk (1 CTA/SM, 196 regs).
#define KC 32
#define SSTRIDE 36
#define STAGE_U32 (128 * SSTRIDE)

template<int EPI>
__global__ __launch_bounds__(256, 1) void tc_gemm(
    const float* __restrict__ A, const float* __restrict__ B,
    const float* __restrict__ bias, const float* __restrict__ res,
    float* __restrict__ C, int M, int N, int K)
{
    __shared__ uint32_t sA[2][STAGE_U32];
    __shared__ uint32_t sB[2][STAGE_U32];

    int tid  = threadIdx.x;
    int wid  = tid >> 5;
    int lane = tid & 31;
    int wm = wid >> 2;
    int wn = wid & 3;
    int gid = lane >> 2;
    int tig = lane & 3;

    int m0 = blockIdx.y * 128, n0 = blockIdx.x * 128;

    int trow = tid >> 3;
    int tseg = tid & 7;

    float acc[4][4][4];
#pragma unroll
    for (int i = 0; i < 4; i++)
#pragma unroll
        for (int j = 0; j < 4; j++)
#pragma unroll
            for (int r = 0; r < 4; r++) acc[i][j][r] = 0.f;

    float4 av[4], bv[4];
#pragma unroll
    for (int p = 0; p < 4; p++) {
        int r = trow + p * 32;
        av[p] = *(const float4*)(A + (size_t)(m0 + r) * K + tseg * 4);
        bv[p] = *(const float4*)(B + (size_t)(n0 + r) * K + tseg * 4);
    }
#pragma unroll
    for (int p = 0; p < 4; p++) {
        int r = trow + p * 32;
        uint32_t* da = &sA[0][r * SSTRIDE + tseg * 4];
        uint32_t* db = &sB[0][r * SSTRIDE + tseg * 4];
        da[0] = f2tf32(av[p].x); da[1] = f2tf32(av[p].y);
        da[2] = f2tf32(av[p].z); da[3] = f2tf32(av[p].w);
        db[0] = f2tf32(bv[p].x); db[1] = f2tf32(bv[p].y);
        db[2] = f2tf32(bv[p].z); db[3] = f2tf32(bv[p].w);
    }
    __syncthreads();

    int Cn = K / KC;
    for (int c = 0; c < Cn; c++) {
        int s = c & 1;
        if (c + 1 < Cn) {
            int k0 = (c + 1) * KC;
#pragma unroll
            for (int p = 0; p < 4; p++) {
                int r = trow + p * 32;
                av[p] = *(const float4*)(A + (size_t)(m0 + r) * K + k0 + tseg * 4);
                bv[p] = *(const float4*)(B + (size_t)(n0 + r) * K + k0 + tseg * 4);
            }
        }

        const uint32_t* As = sA[s];
        const uint32_t* Bs = sB[s];
#pragma unroll
        for (int ks = 0; ks < 4; ks++) {
            int k0 = ks * 8;
            uint32_t afr[4][4], bfr[4][2];
#pragma unroll
            for (int i = 0; i < 4; i++) {
                int rb = wm * 64 + i * 16;
                afr[i][0] = As[(rb + gid    ) * SSTRIDE + k0 + tig];
                afr[i][1] = As[(rb + 8 + gid) * SSTRIDE + k0 + tig];
                afr[i][2] = As[(rb + gid    ) * SSTRIDE + k0 + 4 + tig];
                afr[i][3] = As[(rb + 8 + gid) * SSTRIDE + k0 + 4 + tig];
            }
#pragma unroll
            for (int j = 0; j < 4; j++) {
                int cb = wn * 32 + j * 8;
                bfr[j][0] = Bs[(cb + gid) * SSTRIDE + k0 + tig];
                bfr[j][1] = Bs[(cb + gid) * SSTRIDE + k0 + 4 + tig];
            }
#pragma unroll
            for (int i = 0; i < 4; i++)
#pragma unroll
                for (int j = 0; j < 4; j++)
                    mma_tf32(acc[i][j], afr[i], bfr[j]);
        }

        if (c + 1 < Cn) {
            int s1 = s ^ 1;
#pragma unroll
            for (int p = 0; p < 4; p++) {
                int r = trow + p * 32;
                uint32_t* da = &sA[s1][r * SSTRIDE + tseg * 4];
                uint32_t* db = &sB[s1][r * SSTRIDE + tseg * 4];
                da[0] = f2tf32(av[p].x); da[1] = f2tf32(av[p].y);
                da[2] = f2tf32(av[p].z); da[3] = f2tf32(av[p].w);
                db[0] = f2tf32(bv[p].x); db[1] = f2tf32(bv[p].y);
                db[2] = f2tf32(bv[p].z); db[3] = f2tf32(bv[p].w);
            }
            __syncthreads();
        }
    }

#pragma unroll
    for (int i = 0; i < 4; i++) {
#pragma unroll
        for (int j = 0; j < 4; j++) {
            int col = n0 + wn * 32 + j * 8 + tig * 2;
#pragma unroll
            for (int half = 0; half < 2; half++) {
                int row = m0 + wm * 64 + i * 16 + gid + half * 8;
                float vx = acc[i][j][half * 2 + 0];
                float vy = acc[i][j][half * 2 + 1];
                if (EPI == 1) {
                    const float* rrow = res + (size_t)row * N + col;
                    vx += bias[col]     + rrow[0];
                    vy += bias[col + 1] + rrow[1];
                } else if (EPI == 2) {
                    vx += bias[col];
                    vy += bias[col + 1];
                    vx = 0.5f * vx * (1.0f + erff(vx * 0.70710678118654752f));
                    vy = 0.5f * vy * (1.0f + erff(vy * 0.70710678118654752f));
                }
                float2 o = make_float2(vx, vy);
                *(float2*)(C + (size_t)row * N + col) = o;
            }
        }
    }
}

// ================= Flash attention (one split per block) on tf32 mma =================
// Round-6 proven: grid (8, 12, 8), 8 warps x 16 rows, 2 CTAs/SM.
#define SQ_STR 68
#define SK_STR 68
#define SV_STR 136
#define SQ_SIZE (128*SQ_STR)
#define SK_SIZE (64*SK_STR)
#define SV_SIZE (64*SV_STR)
#define ATT_SMEM ((SQ_SIZE+SK_SIZE+SV_SIZE)*4)

__global__ __launch_bounds__(256, 2) void attn_mma_kernel(
    const float* __restrict__ Q, const float* __restrict__ K,
    const float* __restrict__ Vv, float* __restrict__ O1, float* __restrict__ O2)
{
    extern __shared__ uint32_t asm_[];
    uint32_t* sQ = asm_;
    uint32_t* sK = asm_ + SQ_SIZE;
    uint32_t* sV = asm_ + SQ_SIZE + SK_SIZE;

    int tid  = threadIdx.x;
    int wid  = tid >> 5;
    int lane = tid & 31;
    int gid  = lane >> 2;
    int tig  = lane & 3;

    int q0 = blockIdx.x * 128;
    int h  = blockIdx.y;
    int bz = blockIdx.z;
    int b  = bz >> 1, sp = bz & 1;
    size_t base = (size_t)b * NN;
    int qkcol = h * TWO_D + sp * 64;
    int vcol  = h * TWO_D;
    float* O = sp ? O2 : O1;

    // stage Q (scaled by SCALE), 128 rows x 64 dims
    {
        int c4 = tid & 15, r0 = tid >> 4;
#pragma unroll
        for (int p = 0; p < 8; p++) {
            int r = r0 + p * 16;
            float4 qv = *(const float4*)&Q[(base + q0 + r) * (2*CC) + qkcol + c4 * 4];
            uint32_t* d = &sQ[r * SQ_STR + c4 * 4];
            d[0] = f2tf32(qv.x * SCALE); d[1] = f2tf32(qv.y * SCALE);
            d[2] = f2tf32(qv.z * SCALE); d[3] = f2tf32(qv.w * SCALE);
        }
    }

    float o[16][4];
#pragma unroll
    for (int j = 0; j < 16; j++)
#pragma unroll
        for (int r = 0; r < 4; r++) o[j][r] = 0.f;
    float m0 = -1e30f, m1 = -1e30f, l0 = 0.f, l1 = 0.f;

    for (int t = 0; t < NN / 64; t++) {
        __syncthreads();
#pragma unroll
        for (int p = 0; p < 4; p++) {
            int e = tid + p * 256;
            int r = e >> 4, c4 = e & 15;
            float4 kv = *(const float4*)&K[(base + t*64 + r) * (2*CC) + qkcol + c4 * 4];
            uint32_t* d = &sK[r * SK_STR + c4 * 4];
            d[0] = f2tf32(kv.x); d[1] = f2tf32(kv.y);
            d[2] = f2tf32(kv.z); d[3] = f2tf32(kv.w);
        }
#pragma unroll
        for (int p = 0; p < 8; p++) {
            int e = tid + p * 256;
            int r = e >> 5, c4 = e & 31;
            float4 vv = *(const float4*)&Vv[(base + t*64 + r) * (2*CC) + vcol + c4 * 4];
            uint32_t* d = &sV[r * SV_STR + c4 * 4];
            d[0] = f2tf32(vv.x); d[1] = f2tf32(vv.y);
            d[2] = f2tf32(vv.z); d[3] = f2tf32(vv.w);
        }
        __syncthreads();

        // S = Q K^T (16 rows x 64 keys per warp)
        float s_[8][4];
#pragma unroll
        for (int j = 0; j < 8; j++)
#pragma unroll
            for (int r = 0; r < 4; r++) s_[j][r] = 0.f;
        int ar = wid * 16 + gid;
#pragma unroll
        for (int kc = 0; kc < 8; kc++) {
            uint32_t a[4];
            a[0] = sQ[ ar      * SQ_STR + kc*8 + tig];
            a[1] = sQ[(ar + 8) * SQ_STR + kc*8 + tig];
            a[2] = sQ[ ar      * SQ_STR + kc*8 + 4 + tig];
            a[3] = sQ[(ar + 8) * SQ_STR + kc*8 + 4 + tig];
#pragma unroll
            for (int j = 0; j < 8; j++) {
                uint32_t bfr[2];
                bfr[0] = sK[(j*8 + gid) * SK_STR + kc*8 + tig];
                bfr[1] = sK[(j*8 + gid) * SK_STR + kc*8 + 4 + tig];
                mma_tf32(s_[j], a, bfr);
            }
        }

        // online softmax (rows gid and gid+8 of this warp)
        float rm0 = -1e30f, rm1 = -1e30f;
#pragma unroll
        for (int j = 0; j < 8; j++) {
            rm0 = fmaxf(rm0, fmaxf(s_[j][0], s_[j][1]));
            rm1 = fmaxf(rm1, fmaxf(s_[j][2], s_[j][3]));
        }
        rm0 = fmaxf(rm0, __shfl_xor_sync(0xffffffffu, rm0, 1));
        rm0 = fmaxf(rm0, __shfl_xor_sync(0xffffffffu, rm0, 2));
        rm1 = fmaxf(rm1, __shfl_xor_sync(0xffffffffu, rm1, 1));
        rm1 = fmaxf(rm1, __shfl_xor_sync(0xffffffffu, rm1, 2));
        float nm0 = fmaxf(m0, rm0), nm1 = fmaxf(m1, rm1);
        float f0 = __expf(m0 - nm0), f1 = __expf(m1 - nm1);
        float rs0 = 0.f, rs1 = 0.f;
#pragma unroll
        for (int j = 0; j < 8; j++) {
            s_[j][0] = __expf(s_[j][0] - nm0);
            s_[j][1] = __expf(s_[j][1] - nm0);
            s_[j][2] = __expf(s_[j][2] - nm1);
            s_[j][3] = __expf(s_[j][3] - nm1);
            rs0 += s_[j][0] + s_[j][1];
            rs1 += s_[j][2] + s_[j][3];
        }
        rs0 += __shfl_xor_sync(0xffffffffu, rs0, 1);
        rs0 += __shfl_xor_sync(0xffffffffu, rs0, 2);
        rs1 += __shfl_xor_sync(0xffffffffu, rs1, 1);
        rs1 += __shfl_xor_sync(0xffffffffu, rs1, 2);
        l0 = l0 * f0 + rs0;
        l1 = l1 * f1 + rs1;
        m0 = nm0; m1 = nm1;
#pragma unroll
        for (int j = 0; j < 16; j++) {
            o[j][0] *= f0; o[j][1] *= f0;
            o[j][2] *= f1; o[j][3] *= f1;
        }

        // O += P @ V : re-lay C-fragment P into A-fragments via shuffles
        int srcA = (lane & ~3) | (tig >> 1);
        int srcB = srcA + 2;
        bool odd = (tig & 1);
#pragma unroll
        for (int kc = 0; kc < 8; kc++) {
            float c0 = s_[kc][0], c1 = s_[kc][1], c2 = s_[kc][2], c3 = s_[kc][3];
            float x0 = __shfl_sync(0xffffffffu, c0, srcA);
            float x1 = __shfl_sync(0xffffffffu, c1, srcA);
            float y0 = __shfl_sync(0xffffffffu, c0, srcB);
            float y1 = __shfl_sync(0xffffffffu, c1, srcB);
            float z0 = __shfl_sync(0xffffffffu, c2, srcA);
            float z1 = __shfl_sync(0xffffffffu, c3, srcA);
            float w0 = __shfl_sync(0xffffffffu, c2, srcB);
            float w1 = __shfl_sync(0xffffffffu, c3, srcB);
            uint32_t a[4];
            a[0] = __float_as_uint(odd ? x1 : x0);
            a[1] = __float_as_uint(odd ? z1 : z0);
            a[2] = __float_as_uint(odd ? y1 : y0);
            a[3] = __float_as_uint(odd ? w1 : w0);
#pragma unroll
            for (int j = 0; j < 16; j++) {
                uint32_t bfr[2];
                bfr[0] = sV[(kc*8 +     tig) * SV_STR + j*8 + gid];
                bfr[1] = sV[(kc*8 + 4 + tig) * SV_STR + j*8 + gid];
                mma_tf32(o[j], a, bfr);
            }
        }
    }

    // epilogue: normalize, store split output
    float inv0 = 1.f / l0, inv1 = 1.f / l1;
    int row0 = q0 + wid * 16 + gid, row1 = row0 + 8;
#pragma unroll
    for (int j = 0; j < 16; j++) {
        int col = vcol + j*8 + tig*2;
        *(float2*)&O[(base + row0) * (2*CC) + col] = make_float2(o[j][0]*inv0, o[j][1]*inv0);
        *(float2*)&O[(base + row1) * (2*CC) + col] = make_float2(o[j][2]*inv1, o[j][3]*inv1);
    }
}

// ================= combine: diff + per-head LN(128) + scale =================
__global__ __launch_bounds__(128) void combine_kernel(
    const float* __restrict__ O1, const float* __restrict__ O2,
    const float* __restrict__ lamp, const float* __restrict__ lnw,
    const float* __restrict__ lnb, float* __restrict__ out)
{
    int row = blockIdx.x, h = blockIdx.y, tid = threadIdx.x;
    size_t idx = (size_t)row * (2*CC) + h * TWO_D + tid;
    float lam = lamp[0];
    float v = O1[idx] - lam * O2[idx];
    float s = v, sq = v * v;
#pragma unroll
    for (int off = 16; off >= 1; off >>= 1) {
        s  += __shfl_xor_sync(0xffffffffu, s,  off);
        sq += __shfl_xor_sync(0xffffffffu, sq, off);
    }
    __shared__ float ws[4], wq[4];
    __shared__ float smu, srs;
    int wid = tid >> 5, lane = tid & 31;
    if (lane == 0) { ws[wid] = s; wq[wid] = sq; }
    __syncthreads();
    if (tid == 0) {
        float S = ws[0]+ws[1]+ws[2]+ws[3];
        float Q = wq[0]+wq[1]+wq[2]+wq[3];
        float mu = S * (1.0f/128.0f);
        float var = Q * (1.0f/128.0f) - mu * mu;
        smu = mu; srs = rsqrtf(var + EPS);
    }
    __syncthreads();
    float y = (v - smu) * srs * lnw[tid] + lnb[tid];
    out[idx] = y * OUT_SCALE;
}

// ================= launch =================
extern "C" void kernel_launch(void* const* d_in, const int* in_sizes, int n_in,
                              void* d_out, int out_size)
{
    const float* x    = (const float*)d_in[0];
    const float* n1w  = (const float*)d_in[1];
    const float* n1b  = (const float*)d_in[2];
    const float* wq   = (const float*)d_in[3];
    const float* wk   = (const float*)d_in[4];
    const float* wv   = (const float*)d_in[5];
    const float* lam  = (const float*)d_in[6];
    const float* alnw = (const float*)d_in[7];
    const float* alnb = (const float*)d_in[8];
    const float* pw   = (const float*)d_in[9];
    const float* pb   = (const float*)d_in[10];
    const float* n2w  = (const float*)d_in[11];
    const float* n2b  = (const float*)d_in[12];
    const float* f1w  = (const float*)d_in[13];
    const float* f1b  = (const float*)d_in[14];
    const float* f2w  = (const float*)d_in[15];
    const float* f2b  = (const float*)d_in[16];
    float* out = (float*)d_out;

    float *xn, *q, *k, *v, *o1, *o2, *att, *xmid, *xn2, *hb;
    cudaGetSymbolAddress((void**)&xn,   g_xn);
    cudaGetSymbolAddress((void**)&q,    g_q);
    cudaGetSymbolAddress((void**)&k,    g_k);
    cudaGetSymbolAddress((void**)&v,    g_v);
    cudaGetSymbolAddress((void**)&o1,   g_o1);
    cudaGetSymbolAddress((void**)&o2,   g_o2);
    cudaGetSymbolAddress((void**)&att,  g_att);
    cudaGetSymbolAddress((void**)&xmid, g_xmid);
    cudaGetSymbolAddress((void**)&xn2,  g_xn2);
    cudaGetSymbolAddress((void**)&hb,   g_h);

    cudaFuncSetAttribute(attn_mma_kernel,
                         cudaFuncAttributeMaxDynamicSharedMemorySize, ATT_SMEM);

    // 1. LN1
    ln_kernel<<<MROWS, 256>>>(x, n1w, n1b, xn);
    // 2. QKV GEMMs (4096 x 1536 x 768)
    tc_gemm<0><<<dim3(1536/128, MROWS/128), 256>>>(xn, wq, nullptr, nullptr, q, MROWS, 1536, 768);
    tc_gemm<0><<<dim3(1536/128, MROWS/128), 256>>>(xn, wk, nullptr, nullptr, k, MROWS, 1536, 768);
    tc_gemm<0><<<dim3(1536/128, MROWS/128), 256>>>(xn, wv, nullptr, nullptr, v, MROWS, 1536, 768);
    // 3. flash attention per split on tensor cores
    attn_mma_kernel<<<dim3(NN/128, HH, BB*2), 256, ATT_SMEM>>>(q, k, v, o1, o2);
    // 3b. combine: diff + head-LN + scale
    combine_kernel<<<dim3(MROWS, HH), 128>>>(o1, o2, lam, alnw, alnb, att);
    // 4. proj + bias + residual (4096 x 768 x 1536)
    tc_gemm<1><<<dim3(768/128, MROWS/128), 256>>>(att, pw, pb, x, xmid, MROWS, 768, 1536);
    // 5. LN2
    ln_kernel<<<MROWS, 256>>>(xmid, n2w, n2b, xn2);
    // 6. fc1 + bias + GELU (4096 x 3072 x 768)
    tc_gemm<2><<<dim3(3072/128, MROWS/128), 256>>>(xn2, f1w, f1b, nullptr, hb, MROWS, 3072, 768);
    // 7. fc2 + bias + residual (4096 x 768 x 3072)
    tc_gemm<1><<<dim3(768/128, MROWS/128), 256>>>(hb, f2w, f2b, xmid, out, MROWS, 768, 3072);
}

// round 8
// speedup vs baseline: 1.0279x; 1.0279x over previous
#include <cuda_runtime.h>
#include <math.h>
#include <stdint.h>

// ---------------- problem constants ----------------
#define BB 4
#define NN 1024
#define CC 768
#define HH 12
#define TWO_D 128
#define MROWS (BB*NN)    // 4096
#define SCALE 0.125f     // D^-0.5
#define EPS 1e-5f
#define OUT_SCALE 0.8f   // 1 - LAMBDA_INIT

// ---------------- scratch (device globals; no alloc allowed) ----------------
__device__ float g_xn  [MROWS*CC];
__device__ float g_q   [MROWS*2*CC];
__device__ float g_k   [MROWS*2*CC];
__device__ float g_v   [MROWS*2*CC];
__device__ float g_o1  [MROWS*2*CC];
__device__ float g_o2  [MROWS*2*CC];
__device__ float g_att [MROWS*2*CC];
__device__ float g_xmid[MROWS*CC];
__device__ float g_xn2 [MROWS*CC];
__device__ float g_h   [MROWS*4*CC];

// ================= helpers =================
__device__ __forceinline__ uint32_t f2tf32(float f) {
    uint32_t r;
    asm("cvt.rna.tf32.f32 %0, %1;" : "=r"(r) : "f"(f));
    return r;
}
__device__ __forceinline__ void mma_tf32(float* c, const uint32_t* a, const uint32_t* b) {
    asm volatile("mma.sync.aligned.m16n8k8.row.col.f32.tf32.tf32.f32 "
        "{%0,%1,%2,%3}, {%4,%5,%6,%7}, {%8,%9}, {%0,%1,%2,%3};"
        : "+f"(c[0]), "+f"(c[1]), "+f"(c[2]), "+f"(c[3])
        : "r"(a[0]), "r"(a[1]), "r"(a[2]), "r"(a[3]), "r"(b[0]), "r"(b[1]));
}

// ================= LayerNorm over 768 =================
__global__ __launch_bounds__(256) void ln_kernel(
    const float* __restrict__ x, const float* __restrict__ w,
    const float* __restrict__ b, float* __restrict__ out)
{
    int row = blockIdx.x;
    int tid = threadIdx.x;
    const float* xr = x + (size_t)row * CC;
    float v0 = xr[tid], v1 = xr[tid + 256], v2 = xr[tid + 512];
    float s  = v0 + v1 + v2;
    float sq = v0*v0 + v1*v1 + v2*v2;
#pragma unroll
    for (int off = 16; off >= 1; off >>= 1) {
        s  += __shfl_xor_sync(0xffffffffu, s,  off);
        sq += __shfl_xor_sync(0xffffffffu, sq, off);
    }
    __shared__ float rs_[8], rq_[8];
    __shared__ float smu, srs;
    int wid = tid >> 5, lane = tid & 31;
    if (lane == 0) { rs_[wid] = s; rq_[wid] = sq; }
    __syncthreads();
    if (tid == 0) {
        float S = 0.f, Q = 0.f;
#pragma unroll
        for (int i = 0; i < 8; i++) { S += rs_[i]; Q += rq_[i]; }
        float mu = S / (float)CC;
        float var = Q / (float)CC - mu * mu;
        smu = mu; srs = rsqrtf(var + EPS);
    }
    __syncthreads();
    float mu = smu, r = srs;
    float* orow = out + (size_t)row * CC;
    orow[tid]       = (v0 - mu) * r * w[tid]       + b[tid];
    orow[tid + 256] = (v1 - mu) * r * w[tid + 256] + b[tid + 256];
    orow[tid + 512] = (v2 - mu) * r * w[tid + 512] + b[tid + 512];
}

// ================= TF32 mma.sync GEMM core =================
// 128x128 tile, 8 warps (2m x 4n), 64x32 warp tile, double-buffered smem,
// register prefetch of next chunk (1 CTA/SM, ~196 regs). Proven at 87us/QKV.
#define KC 32
#define SSTRIDE 36
#define STAGE_U32 (128 * SSTRIDE)

template<int EPI>
__device__ __forceinline__ void gemm_body(
    const float* __restrict__ A, const float* __restrict__ B,
    const float* __restrict__ bias, const float* __restrict__ res,
    float* __restrict__ C, int M, int N, int K, int bx, int by)
{
    __shared__ uint32_t sA[2][STAGE_U32];
    __shared__ uint32_t sB[2][STAGE_U32];

    int tid  = threadIdx.x;
    int wid  = tid >> 5;
    int lane = tid & 31;
    int wm = wid >> 2;
    int wn = wid & 3;
    int gid = lane >> 2;
    int tig = lane & 3;

    int m0 = by * 128, n0 = bx * 128;

    int trow = tid >> 3;
    int tseg = tid & 7;

    float acc[4][4][4];
#pragma unroll
    for (int i = 0; i < 4; i++)
#pragma unroll
        for (int j = 0; j < 4; j++)
#pragma unroll
            for (int r = 0; r < 4; r++) acc[i][j][r] = 0.f;

    float4 av[4], bv[4];
#pragma unroll
    for (int p = 0; p < 4; p++) {
        int r = trow + p * 32;
        av[p] = *(const float4*)(A + (size_t)(m0 + r) * K + tseg * 4);
        bv[p] = *(const float4*)(B + (size_t)(n0 + r) * K + tseg * 4);
    }
#pragma unroll
    for (int p = 0; p < 4; p++) {
        int r = trow + p * 32;
        uint32_t* da = &sA[0][r * SSTRIDE + tseg * 4];
        uint32_t* db = &sB[0][r * SSTRIDE + tseg * 4];
        da[0] = f2tf32(av[p].x); da[1] = f2tf32(av[p].y);
        da[2] = f2tf32(av[p].z); da[3] = f2tf32(av[p].w);
        db[0] = f2tf32(bv[p].x); db[1] = f2tf32(bv[p].y);
        db[2] = f2tf32(bv[p].z); db[3] = f2tf32(bv[p].w);
    }
    __syncthreads();

    int Cn = K / KC;
    for (int c = 0; c < Cn; c++) {
        int s = c & 1;
        if (c + 1 < Cn) {
            int k0 = (c + 1) * KC;
#pragma unroll
            for (int p = 0; p < 4; p++) {
                int r = trow + p * 32;
                av[p] = *(const float4*)(A + (size_t)(m0 + r) * K + k0 + tseg * 4);
                bv[p] = *(const float4*)(B + (size_t)(n0 + r) * K + k0 + tseg * 4);
            }
        }

        const uint32_t* As = sA[s];
        const uint32_t* Bs = sB[s];
#pragma unroll
        for (int ks = 0; ks < 4; ks++) {
            int k0 = ks * 8;
            uint32_t afr[4][4], bfr[4][2];
#pragma unroll
            for (int i = 0; i < 4; i++) {
                int rb = wm * 64 + i * 16;
                afr[i][0] = As[(rb + gid    ) * SSTRIDE + k0 + tig];
                afr[i][1] = As[(rb + 8 + gid) * SSTRIDE + k0 + tig];
                afr[i][2] = As[(rb + gid    ) * SSTRIDE + k0 + 4 + tig];
                afr[i][3] = As[(rb + 8 + gid) * SSTRIDE + k0 + 4 + tig];
            }
#pragma unroll
            for (int j = 0; j < 4; j++) {
                int cb = wn * 32 + j * 8;
                bfr[j][0] = Bs[(cb + gid) * SSTRIDE + k0 + tig];
                bfr[j][1] = Bs[(cb + gid) * SSTRIDE + k0 + 4 + tig];
            }
#pragma unroll
            for (int i = 0; i < 4; i++)
#pragma unroll
                for (int j = 0; j < 4; j++)
                    mma_tf32(acc[i][j], afr[i], bfr[j]);
        }

        if (c + 1 < Cn) {
            int s1 = s ^ 1;
#pragma unroll
            for (int p = 0; p < 4; p++) {
                int r = trow + p * 32;
                uint32_t* da = &sA[s1][r * SSTRIDE + tseg * 4];
                uint32_t* db = &sB[s1][r * SSTRIDE + tseg * 4];
                da[0] = f2tf32(av[p].x); da[1] = f2tf32(av[p].y);
                da[2] = f2tf32(av[p].z); da[3] = f2tf32(av[p].w);
                db[0] = f2tf32(bv[p].x); db[1] = f2tf32(bv[p].y);
                db[2] = f2tf32(bv[p].z); db[3] = f2tf32(bv[p].w);
            }
            __syncthreads();
        }
    }

#pragma unroll
    for (int i = 0; i < 4; i++) {
#pragma unroll
        for (int j = 0; j < 4; j++) {
            int col = n0 + wn * 32 + j * 8 + tig * 2;
#pragma unroll
            for (int half = 0; half < 2; half++) {
                int row = m0 + wm * 64 + i * 16 + gid + half * 8;
                float vx = acc[i][j][half * 2 + 0];
                float vy = acc[i][j][half * 2 + 1];
                if (EPI == 1) {
                    const float* rrow = res + (size_t)row * N + col;
                    vx += bias[col]     + rrow[0];
                    vy += bias[col + 1] + rrow[1];
                } else if (EPI == 2) {
                    vx += bias[col];
                    vy += bias[col + 1];
                    vx = 0.5f * vx * (1.0f + erff(vx * 0.70710678118654752f));
                    vy = 0.5f * vy * (1.0f + erff(vy * 0.70710678118654752f));
                }
                float2 o = make_float2(vx, vy);
                *(float2*)(C + (size_t)row * N + col) = o;
            }
        }
    }
}

template<int EPI>
__global__ __launch_bounds__(256, 1) void tc_gemm(
    const float* __restrict__ A, const float* __restrict__ B,
    const float* __restrict__ bias, const float* __restrict__ res,
    float* __restrict__ C, int M, int N, int K)
{
    gemm_body<EPI>(A, B, bias, res, C, M, N, K, blockIdx.x, blockIdx.y);
}

// Merged QKV: one launch, z selects weight/output. 1152 CTAs = one big wave set.
__global__ __launch_bounds__(256, 1) void qkv_gemm(
    const float* __restrict__ A,
    const float* __restrict__ Wq, const float* __restrict__ Wk, const float* __restrict__ Wv,
    float* __restrict__ Oq, float* __restrict__ Ok, float* __restrict__ Ov)
{
    const float* B;
    float* C;
    int z = blockIdx.z;
    if (z == 0)      { B = Wq; C = Oq; }
    else if (z == 1) { B = Wk; C = Ok; }
    else             { B = Wv; C = Ov; }
    gemm_body<0>(A, B, nullptr, nullptr, C, MROWS, 2*CC, CC, blockIdx.x, blockIdx.y);
}

// ================= Flash attention (one split per block) on tf32 mma =================
// grid (8, 12, 8), 8 warps x 16 rows, 2 CTAs/SM. Proven round 6.
#define SQ_STR 68
#define SK_STR 68
#define SV_STR 136
#define SQ_SIZE (128*SQ_STR)
#define SK_SIZE (64*SK_STR)
#define SV_SIZE (64*SV_STR)
#define ATT_SMEM ((SQ_SIZE+SK_SIZE+SV_SIZE)*4)

__global__ __launch_bounds__(256, 2) void attn_mma_kernel(
    const float* __restrict__ Q, const float* __restrict__ K,
    const float* __restrict__ Vv, float* __restrict__ O1, float* __restrict__ O2)
{
    extern __shared__ uint32_t asm_[];
    uint32_t* sQ = asm_;
    uint32_t* sK = asm_ + SQ_SIZE;
    uint32_t* sV = asm_ + SQ_SIZE + SK_SIZE;

    int tid  = threadIdx.x;
    int wid  = tid >> 5;
    int lane = tid & 31;
    int gid  = lane >> 2;
    int tig  = lane & 3;

    int q0 = blockIdx.x * 128;
    int h  = blockIdx.y;
    int bz = blockIdx.z;
    int b  = bz >> 1, sp = bz & 1;
    size_t base = (size_t)b * NN;
    int qkcol = h * TWO_D + sp * 64;
    int vcol  = h * TWO_D;
    float* O = sp ? O2 : O1;

    {
        int c4 = tid & 15, r0 = tid >> 4;
#pragma unroll
        for (int p = 0; p < 8; p++) {
            int r = r0 + p * 16;
            float4 qv = *(const float4*)&Q[(base + q0 + r) * (2*CC) + qkcol + c4 * 4];
            uint32_t* d = &sQ[r * SQ_STR + c4 * 4];
            d[0] = f2tf32(qv.x * SCALE); d[1] = f2tf32(qv.y * SCALE);
            d[2] = f2tf32(qv.z * SCALE); d[3] = f2tf32(qv.w * SCALE);
        }
    }

    float o[16][4];
#pragma unroll
    for (int j = 0; j < 16; j++)
#pragma unroll
        for (int r = 0; r < 4; r++) o[j][r] = 0.f;
    float m0 = -1e30f, m1 = -1e30f, l0 = 0.f, l1 = 0.f;

    for (int t = 0; t < NN / 64; t++) {
        __syncthreads();
#pragma unroll
        for (int p = 0; p < 4; p++) {
            int e = tid + p * 256;
            int r = e >> 4, c4 = e & 15;
            float4 kv = *(const float4*)&K[(base + t*64 + r) * (2*CC) + qkcol + c4 * 4];
            uint32_t* d = &sK[r * SK_STR + c4 * 4];
            d[0] = f2tf32(kv.x); d[1] = f2tf32(kv.y);
            d[2] = f2tf32(kv.z); d[3] = f2tf32(kv.w);
        }
#pragma unroll
        for (int p = 0; p < 8; p++) {
            int e = tid + p * 256;
            int r = e >> 5, c4 = e & 31;
            float4 vv = *(const float4*)&Vv[(base + t*64 + r) * (2*CC) + vcol + c4 * 4];
            uint32_t* d = &sV[r * SV_STR + c4 * 4];
            d[0] = f2tf32(vv.x); d[1] = f2tf32(vv.y);
            d[2] = f2tf32(vv.z); d[3] = f2tf32(vv.w);
        }
        __syncthreads();

        float s_[8][4];
#pragma unroll
        for (int j = 0; j < 8; j++)
#pragma unroll
            for (int r = 0; r < 4; r++) s_[j][r] = 0.f;
        int ar = wid * 16 + gid;
#pragma unroll
        for (int kc = 0; kc < 8; kc++) {
            uint32_t a[4];
            a[0] = sQ[ ar      * SQ_STR + kc*8 + tig];
            a[1] = sQ[(ar + 8) * SQ_STR + kc*8 + tig];
            a[2] = sQ[ ar      * SQ_STR + kc*8 + 4 + tig];
            a[3] = sQ[(ar + 8) * SQ_STR + kc*8 + 4 + tig];
#pragma unroll
            for (int j = 0; j < 8; j++) {
                uint32_t bfr[2];
                bfr[0] = sK[(j*8 + gid) * SK_STR + kc*8 + tig];
                bfr[1] = sK[(j*8 + gid) * SK_STR + kc*8 + 4 + tig];
                mma_tf32(s_[j], a, bfr);
            }
        }

        float rm0 = -1e30f, rm1 = -1e30f;
#pragma unroll
        for (int j = 0; j < 8; j++) {
            rm0 = fmaxf(rm0, fmaxf(s_[j][0], s_[j][1]));
            rm1 = fmaxf(rm1, fmaxf(s_[j][2], s_[j][3]));
        }
        rm0 = fmaxf(rm0, __shfl_xor_sync(0xffffffffu, rm0, 1));
        rm0 = fmaxf(rm0, __shfl_xor_sync(0xffffffffu, rm0, 2));
        rm1 = fmaxf(rm1, __shfl_xor_sync(0xffffffffu, rm1, 1));
        rm1 = fmaxf(rm1, __shfl_xor_sync(0xffffffffu, rm1, 2));
        float nm0 = fmaxf(m0, rm0), nm1 = fmaxf(m1, rm1);
        float f0 = __expf(m0 - nm0), f1 = __expf(m1 - nm1);
        float rs0 = 0.f, rs1 = 0.f;
#pragma unroll
        for (int j = 0; j < 8; j++) {
            s_[j][0] = __expf(s_[j][0] - nm0);
            s_[j][1] = __expf(s_[j][1] - nm0);
            s_[j][2] = __expf(s_[j][2] - nm1);
            s_[j][3] = __expf(s_[j][3] - nm1);
            rs0 += s_[j][0] + s_[j][1];
            rs1 += s_[j][2] + s_[j][3];
        }
        rs0 += __shfl_xor_sync(0xffffffffu, rs0, 1);
        rs0 += __shfl_xor_sync(0xffffffffu, rs0, 2);
        rs1 += __shfl_xor_sync(0xffffffffu, rs1, 1);
        rs1 += __shfl_xor_sync(0xffffffffu, rs1, 2);
        l0 = l0 * f0 + rs0;
        l1 = l1 * f1 + rs1;
        m0 = nm0; m1 = nm1;
#pragma unroll
        for (int j = 0; j < 16; j++) {
            o[j][0] *= f0; o[j][1] *= f0;
            o[j][2] *= f1; o[j][3] *= f1;
        }

        int srcA = (lane & ~3) | (tig >> 1);
        int srcB = srcA + 2;
        bool odd = (tig & 1);
#pragma unroll
        for (int kc = 0; kc < 8; kc++) {
            float c0 = s_[kc][0], c1 = s_[kc][1], c2 = s_[kc][2], c3 = s_[kc][3];
            float x0 = __shfl_sync(0xffffffffu, c0, srcA);
            float x1 = __shfl_sync(0xffffffffu, c1, srcA);
            float y0 = __shfl_sync(0xffffffffu, c0, srcB);
            float y1 = __shfl_sync(0xffffffffu, c1, srcB);
            float z0 = __shfl_sync(0xffffffffu, c2, srcA);
            float z1 = __shfl_sync(0xffffffffu, c3, srcA);
            float w0 = __shfl_sync(0xffffffffu, c2, srcB);
            float w1 = __shfl_sync(0xffffffffu, c3, srcB);
            uint32_t a[4];
            a[0] = __float_as_uint(odd ? x1 : x0);
            a[1] = __float_as_uint(odd ? z1 : z0);
            a[2] = __float_as_uint(odd ? y1 : y0);
            a[3] = __float_as_uint(odd ? w1 : w0);
#pragma unroll
            for (int j = 0; j < 16; j++) {
                uint32_t bfr[2];
                bfr[0] = sV[(kc*8 +     tig) * SV_STR + j*8 + gid];
                bfr[1] = sV[(kc*8 + 4 + tig) * SV_STR + j*8 + gid];
                mma_tf32(o[j], a, bfr);
            }
        }
    }

    float inv0 = 1.f / l0, inv1 = 1.f / l1;
    int row0 = q0 + wid * 16 + gid, row1 = row0 + 8;
#pragma unroll
    for (int j = 0; j < 16; j++) {
        int col = vcol + j*8 + tig*2;
        *(float2*)&O[(base + row0) * (2*CC) + col] = make_float2(o[j][0]*inv0, o[j][1]*inv0);
        *(float2*)&O[(base + row1) * (2*CC) + col] = make_float2(o[j][2]*inv1, o[j][3]*inv1);
    }
}

// ================= combine: diff + per-head LN(128) + scale =================
__global__ __launch_bounds__(128) void combine_kernel(
    const float* __restrict__ O1, const float* __restrict__ O2,
    const float* __restrict__ lamp, const float* __restrict__ lnw,
    const float* __restrict__ lnb, float* __restrict__ out)
{
    int row = blockIdx.x, h = blockIdx.y, tid = threadIdx.x;
    size_t idx = (size_t)row * (2*CC) + h * TWO_D + tid;
    float lam = lamp[0];
    float v = O1[idx] - lam * O2[idx];
    float s = v, sq = v * v;
#pragma unroll
    for (int off = 16; off >= 1; off >>= 1) {
        s  += __shfl_xor_sync(0xffffffffu, s,  off);
        sq += __shfl_xor_sync(0xffffffffu, sq, off);
    }
    __shared__ float ws[4], wq[4];
    __shared__ float smu, srs;
    int wid = tid >> 5, lane = tid & 31;
    if (lane == 0) { ws[wid] = s; wq[wid] = sq; }
    __syncthreads();
    if (tid == 0) {
        float S = ws[0]+ws[1]+ws[2]+ws[3];
        float Q = wq[0]+wq[1]+wq[2]+wq[3];
        float mu = S * (1.0f/128.0f);
        float var = Q * (1.0f/128.0f) - mu * mu;
        smu = mu; srs = rsqrtf(var + EPS);
    }
    __syncthreads();
    float y = (v - smu) * srs * lnw[tid] + lnb[tid];
    out[idx] = y * OUT_SCALE;
}

// ================= launch =================
extern "C" void kernel_launch(void* const* d_in, const int* in_sizes, int n_in,
                              void* d_out, int out_size)
{
    const float* x    = (const float*)d_in[0];
    const float* n1w  = (const float*)d_in[1];
    const float* n1b  = (const float*)d_in[2];
    const float* wq   = (const float*)d_in[3];
    const float* wk   = (const float*)d_in[4];
    const float* wv   = (const float*)d_in[5];
    const float* lam  = (const float*)d_in[6];
    const float* alnw = (const float*)d_in[7];
    const float* alnb = (const float*)d_in[8];
    const float* pw   = (const float*)d_in[9];
    const float* pb   = (const float*)d_in[10];
    const float* n2w  = (const float*)d_in[11];
    const float* n2b  = (const float*)d_in[12];
    const float* f1w  = (const float*)d_in[13];
    const float* f1b  = (const float*)d_in[14];
    const float* f2w  = (const float*)d_in[15];
    const float* f2b  = (const float*)d_in[16];
    float* out = (float*)d_out;

    float *xn, *q, *k, *v, *o1, *o2, *att, *xmid, *xn2, *hb;
    cudaGetSymbolAddress((void**)&xn,   g_xn);
    cudaGetSymbolAddress((void**)&q,    g_q);
    cudaGetSymbolAddress((void**)&k,    g_k);
    cudaGetSymbolAddress((void**)&v,    g_v);
    cudaGetSymbolAddress((void**)&o1,   g_o1);
    cudaGetSymbolAddress((void**)&o2,   g_o2);
    cudaGetSymbolAddress((void**)&att,  g_att);
    cudaGetSymbolAddress((void**)&xmid, g_xmid);
    cudaGetSymbolAddress((void**)&xn2,  g_xn2);
    cudaGetSymbolAddress((void**)&hb,   g_h);

    cudaFuncSetAttribute(attn_mma_kernel,
                         cudaFuncAttributeMaxDynamicSharedMemorySize, ATT_SMEM);

    // 1. LN1
    ln_kernel<<<MROWS, 256>>>(x, n1w, n1b, xn);
    // 2. merged QKV GEMM (3 x 4096 x 1536 x 768), one launch
    qkv_gemm<<<dim3(1536/128, MROWS/128, 3), 256>>>(xn, wq, wk, wv, q, k, v);
    // 3. flash attention per split on tensor cores
    attn_mma_kernel<<<dim3(NN/128, HH, BB*2), 256, ATT_SMEM>>>(q, k, v, o1, o2);
    // 3b. combine: diff + head-LN + scale
    combine_kernel<<<dim3(MROWS, HH), 128>>>(o1, o2, lam, alnw, alnb, att);
    // 4. proj + bias + residual (4096 x 768 x 1536)
    tc_gemm<1><<<dim3(768/128, MROWS/128), 256>>>(att, pw, pb, x, xmid, MROWS, 768, 1536);
    // 5. LN2
    ln_kernel<<<MROWS, 256>>>(xmid, n2w, n2b, xn2);
    // 6. fc1 + bias + GELU (4096 x 3072 x 768)
    tc_gemm<2><<<dim3(3072/128, MROWS/128), 256>>>(xn2, f1w, f1b, nullptr, hb, MROWS, 3072, 768);
    // 7. fc2 + bias + residual (4096 x 768 x 3072)
    tc_gemm<1><<<dim3(768/128, MROWS/128), 256>>>(hb, f2w, f2b, xmid, out, MROWS, 768, 3072);
}

// round 9
// speedup vs baseline: 1.0767x; 1.0475x over previous
#include <cuda_runtime.h>
#include <math.h>
#include <stdint.h>

// ---------------- problem constants ----------------
#define BB 4
#define NN 1024
#define CC 768
#define HH 12
#define TWO_D 128
#define MROWS (BB*NN)    // 4096
#define SCALE 0.125f     // D^-0.5
#define EPS 1e-5f
#define OUT_SCALE 0.8f   // 1 - LAMBDA_INIT

// ---------------- scratch (device globals; no alloc allowed) ----------------
__device__ float g_xn  [MROWS*CC];
__device__ float g_q   [MROWS*2*CC];
__device__ float g_k   [MROWS*2*CC];
__device__ float g_v   [MROWS*2*CC];
__device__ float g_o1  [MROWS*2*CC];
__device__ float g_o2  [MROWS*2*CC];
__device__ float g_att [MROWS*2*CC];
__device__ float g_xmid[MROWS*CC];
__device__ float g_xn2 [MROWS*CC];
__device__ float g_h   [MROWS*4*CC];
// converted (tf32-rounded) weights
__device__ float g_wq [2*CC*CC];
__device__ float g_wk [2*CC*CC];
__device__ float g_wv [2*CC*CC];
__device__ float g_pw [CC*2*CC];
__device__ float g_f1 [4*CC*CC];
__device__ float g_f2 [CC*4*CC];

// ================= helpers =================
__device__ __forceinline__ uint32_t f2tf32(float f) {
    uint32_t r;
    asm("cvt.rna.tf32.f32 %0, %1;" : "=r"(r) : "f"(f));
    return r;
}
__device__ __forceinline__ float f2tf32f(float f) {
    return __uint_as_float(f2tf32(f));
}
__device__ __forceinline__ void mma_tf32(float* c, const uint32_t* a, const uint32_t* b) {
    asm volatile("mma.sync.aligned.m16n8k8.row.col.f32.tf32.tf32.f32 "
        "{%0,%1,%2,%3}, {%4,%5,%6,%7}, {%8,%9}, {%0,%1,%2,%3};"
        : "+f"(c[0]), "+f"(c[1]), "+f"(c[2]), "+f"(c[3])
        : "r"(a[0]), "r"(a[1]), "r"(a[2]), "r"(a[3]), "r"(b[0]), "r"(b[1]));
}
__device__ __forceinline__ uint32_t smem_u32(const void* p) {
    uint32_t a;
    asm("{ .reg .u64 t; cvta.to.shared.u64 t, %1; cvt.u32.u64 %0, t; }" : "=r"(a) : "l"(p));
    return a;
}
__device__ __forceinline__ void cp16(uint32_t dst, const void* src) {
    asm volatile("cp.async.ca.shared.global [%0], [%1], 16;" :: "r"(dst), "l"(src));
}
__device__ __forceinline__ void cp_commit() {
    asm volatile("cp.async.commit_group;" ::: "memory");
}
__device__ __forceinline__ void cp_wait1() {
    asm volatile("cp.async.wait_group 1;" ::: "memory");
}

// ================= weight tf32 pre-conversion =================
__global__ __launch_bounds__(256) void cvtw_kernel(
    const float* __restrict__ s, float* __restrict__ d, int n4)
{
    int i = blockIdx.x * 256 + threadIdx.x;
    if (i < n4) {
        float4 v = ((const float4*)s)[i];
        v.x = f2tf32f(v.x); v.y = f2tf32f(v.y);
        v.z = f2tf32f(v.z); v.w = f2tf32f(v.w);
        ((float4*)d)[i] = v;
    }
}

// ================= LayerNorm over 768 (output tf32-rounded) =================
__global__ __launch_bounds__(256) void ln_kernel(
    const float* __restrict__ x, const float* __restrict__ w,
    const float* __restrict__ b, float* __restrict__ out)
{
    int row = blockIdx.x;
    int tid = threadIdx.x;
    const float* xr = x + (size_t)row * CC;
    float v0 = xr[tid], v1 = xr[tid + 256], v2 = xr[tid + 512];
    float s  = v0 + v1 + v2;
    float sq = v0*v0 + v1*v1 + v2*v2;
#pragma unroll
    for (int off = 16; off >= 1; off >>= 1) {
        s  += __shfl_xor_sync(0xffffffffu, s,  off);
        sq += __shfl_xor_sync(0xffffffffu, sq, off);
    }
    __shared__ float rs_[8], rq_[8];
    __shared__ float smu, srs;
    int wid = tid >> 5, lane = tid & 31;
    if (lane == 0) { rs_[wid] = s; rq_[wid] = sq; }
    __syncthreads();
    if (tid == 0) {
        float S = 0.f, Q = 0.f;
#pragma unroll
        for (int i = 0; i < 8; i++) { S += rs_[i]; Q += rq_[i]; }
        float mu = S / (float)CC;
        float var = Q / (float)CC - mu * mu;
        smu = mu; srs = rsqrtf(var + EPS);
    }
    __syncthreads();
    float mu = smu, r = srs;
    float* orow = out + (size_t)row * CC;
    orow[tid]       = f2tf32f((v0 - mu) * r * w[tid]       + b[tid]);
    orow[tid + 256] = f2tf32f((v1 - mu) * r * w[tid + 256] + b[tid + 256]);
    orow[tid + 512] = f2tf32f((v2 - mu) * r * w[tid + 512] + b[tid + 512]);
}

// ================= TF32 mma.sync GEMM with cp.async 3-stage pipeline ========
// Inputs A,B must already be tf32-rounded f32. 128x128 tile, 8 warps (2m x 4n).
#define KC 32
#define SSTRIDE 36
#define STAGE_U32 (128 * SSTRIDE)
#define STAGE_BYTES (STAGE_U32 * 4)
#define GSTAGES 3
#define GEMM_SMEM_BYTES (GSTAGES * 2 * STAGE_BYTES)   // 110592

template<int EPI>
__device__ __forceinline__ void gemm_body(
    const float* __restrict__ A, const float* __restrict__ B,
    const float* __restrict__ bias, const float* __restrict__ res,
    float* __restrict__ C, int M, int N, int K, int bx, int by)
{
    extern __shared__ uint32_t gsm[];
    uint32_t sb = smem_u32(gsm);

    int tid  = threadIdx.x;
    int wid  = tid >> 5;
    int lane = tid & 31;
    int wm = wid >> 2;
    int wn = wid & 3;
    int gid = lane >> 2;
    int tig = lane & 3;

    int m0 = by * 128, n0 = bx * 128;
    int trow = tid >> 3;     // 0..31
    int tseg = tid & 7;      // 0..7

    float acc[4][4][4];
#pragma unroll
    for (int i = 0; i < 4; i++)
#pragma unroll
        for (int j = 0; j < 4; j++)
#pragma unroll
            for (int r = 0; r < 4; r++) acc[i][j][r] = 0.f;

    int Cn = K / KC;

    // stage issuer
    auto issue = [&](int c) {
        int s = c % GSTAGES;
        uint32_t abase = sb + (uint32_t)s * 2u * STAGE_BYTES;
        uint32_t bbase = abase + STAGE_BYTES;
        int k0 = c * KC;
#pragma unroll
        for (int p = 0; p < 4; p++) {
            int r = trow + p * 32;
            uint32_t soff = (uint32_t)(r * SSTRIDE + tseg * 4) * 4u;
            cp16(abase + soff, A + (size_t)(m0 + r) * K + k0 + tseg * 4);
            cp16(bbase + soff, B + (size_t)(n0 + r) * K + k0 + tseg * 4);
        }
    };

    issue(0); cp_commit();
    issue(1); cp_commit();

    for (int c = 0; c < Cn; c++) {
        cp_wait1();
        __syncthreads();
        if (c + 2 < Cn) issue(c + 2);
        cp_commit();   // always commit (empty groups keep the count uniform)

        const uint32_t* As = gsm + (size_t)(c % GSTAGES) * 2u * STAGE_U32;
        const uint32_t* Bs = As + STAGE_U32;
#pragma unroll
        for (int ks = 0; ks < 4; ks++) {
            int k0 = ks * 8;
            uint32_t afr[4][4], bfr[4][2];
#pragma unroll
            for (int i = 0; i < 4; i++) {
                int rb = wm * 64 + i * 16;
                afr[i][0] = As[(rb + gid    ) * SSTRIDE + k0 + tig];
                afr[i][1] = As[(rb + 8 + gid) * SSTRIDE + k0 + tig];
                afr[i][2] = As[(rb + gid    ) * SSTRIDE + k0 + 4 + tig];
                afr[i][3] = As[(rb + 8 + gid) * SSTRIDE + k0 + 4 + tig];
            }
#pragma unroll
            for (int j = 0; j < 4; j++) {
                int cb = wn * 32 + j * 8;
                bfr[j][0] = Bs[(cb + gid) * SSTRIDE + k0 + tig];
                bfr[j][1] = Bs[(cb + gid) * SSTRIDE + k0 + 4 + tig];
            }
#pragma unroll
            for (int i = 0; i < 4; i++)
#pragma unroll
                for (int j = 0; j < 4; j++)
                    mma_tf32(acc[i][j], afr[i], bfr[j]);
        }
    }

#pragma unroll
    for (int i = 0; i < 4; i++) {
#pragma unroll
        for (int j = 0; j < 4; j++) {
            int col = n0 + wn * 32 + j * 8 + tig * 2;
#pragma unroll
            for (int half = 0; half < 2; half++) {
                int row = m0 + wm * 64 + i * 16 + gid + half * 8;
                float vx = acc[i][j][half * 2 + 0];
                float vy = acc[i][j][half * 2 + 1];
                if (EPI == 1) {
                    const float* rrow = res + (size_t)row * N + col;
                    vx += bias[col]     + rrow[0];
                    vy += bias[col + 1] + rrow[1];
                } else if (EPI == 2) {
                    vx += bias[col];
                    vy += bias[col + 1];
                    vx = 0.5f * vx * (1.0f + erff(vx * 0.70710678118654752f));
                    vy = 0.5f * vy * (1.0f + erff(vy * 0.70710678118654752f));
                    vx = f2tf32f(vx);   // feeds fc2 GEMM
                    vy = f2tf32f(vy);
                }
                float2 o = make_float2(vx, vy);
                *(float2*)(C + (size_t)row * N + col) = o;
            }
        }
    }
}

template<int EPI>
__global__ __launch_bounds__(256, 1) void tc_gemm(
    const float* __restrict__ A, const float* __restrict__ B,
    const float* __restrict__ bias, const float* __restrict__ res,
    float* __restrict__ C, int M, int N, int K)
{
    gemm_body<EPI>(A, B, bias, res, C, M, N, K, blockIdx.x, blockIdx.y);
}

// Merged QKV: one launch, z selects weight/output.
__global__ __launch_bounds__(256, 1) void qkv_gemm(
    const float* __restrict__ A,
    const float* __restrict__ Wq, const float* __restrict__ Wk, const float* __restrict__ Wv,
    float* __restrict__ Oq, float* __restrict__ Ok, float* __restrict__ Ov)
{
    const float* B;
    float* C;
    int z = blockIdx.z;
    if (z == 0)      { B = Wq; C = Oq; }
    else if (z == 1) { B = Wk; C = Ok; }
    else             { B = Wv; C = Ov; }
    gemm_body<0>(A, B, nullptr, nullptr, C, MROWS, 2*CC, CC, blockIdx.x, blockIdx.y);
}

// ================= Flash attention (one split per block) on tf32 mma =================
// grid (8, 12, 8), 8 warps x 16 rows, 2 CTAs/SM. Proven round 6.
#define SQ_STR 68
#define SK_STR 68
#define SV_STR 136
#define SQ_SIZE (128*SQ_STR)
#define SK_SIZE (64*SK_STR)
#define SV_SIZE (64*SV_STR)
#define ATT_SMEM ((SQ_SIZE+SK_SIZE+SV_SIZE)*4)

__global__ __launch_bounds__(256, 2) void attn_mma_kernel(
    const float* __restrict__ Q, const float* __restrict__ K,
    const float* __restrict__ Vv, float* __restrict__ O1, float* __restrict__ O2)
{
    extern __shared__ uint32_t asm_[];
    uint32_t* sQ = asm_;
    uint32_t* sK = asm_ + SQ_SIZE;
    uint32_t* sV = asm_ + SQ_SIZE + SK_SIZE;

    int tid  = threadIdx.x;
    int wid  = tid >> 5;
    int lane = tid & 31;
    int gid  = lane >> 2;
    int tig  = lane & 3;

    int q0 = blockIdx.x * 128;
    int h  = blockIdx.y;
    int bz = blockIdx.z;
    int b  = bz >> 1, sp = bz & 1;
    size_t base = (size_t)b * NN;
    int qkcol = h * TWO_D + sp * 64;
    int vcol  = h * TWO_D;
    float* O = sp ? O2 : O1;

    {
        int c4 = tid & 15, r0 = tid >> 4;
#pragma unroll
        for (int p = 0; p < 8; p++) {
            int r = r0 + p * 16;
            float4 qv = *(const float4*)&Q[(base + q0 + r) * (2*CC) + qkcol + c4 * 4];
            uint32_t* d = &sQ[r * SQ_STR + c4 * 4];
            d[0] = f2tf32(qv.x * SCALE); d[1] = f2tf32(qv.y * SCALE);
            d[2] = f2tf32(qv.z * SCALE); d[3] = f2tf32(qv.w * SCALE);
        }
    }

    float o[16][4];
#pragma unroll
    for (int j = 0; j < 16; j++)
#pragma unroll
        for (int r = 0; r < 4; r++) o[j][r] = 0.f;
    float m0 = -1e30f, m1 = -1e30f, l0 = 0.f, l1 = 0.f;

    for (int t = 0; t < NN / 64; t++) {
        __syncthreads();
#pragma unroll
        for (int p = 0; p < 4; p++) {
            int e = tid + p * 256;
            int r = e >> 4, c4 = e & 15;
            float4 kv = *(const float4*)&K[(base + t*64 + r) * (2*CC) + qkcol + c4 * 4];
            uint32_t* d = &sK[r * SK_STR + c4 * 4];
            d[0] = f2tf32(kv.x); d[1] = f2tf32(kv.y);
            d[2] = f2tf32(kv.z); d[3] = f2tf32(kv.w);
        }
#pragma unroll
        for (int p = 0; p < 8; p++) {
            int e = tid + p * 256;
            int r = e >> 5, c4 = e & 31;
            float4 vv = *(const float4*)&Vv[(base + t*64 + r) * (2*CC) + vcol + c4 * 4];
            uint32_t* d = &sV[r * SV_STR + c4 * 4];
            d[0] = f2tf32(vv.x); d[1] = f2tf32(vv.y);
            d[2] = f2tf32(vv.z); d[3] = f2tf32(vv.w);
        }
        __syncthreads();

        float s_[8][4];
#pragma unroll
        for (int j = 0; j < 8; j++)
#pragma unroll
            for (int r = 0; r < 4; r++) s_[j][r] = 0.f;
        int ar = wid * 16 + gid;
#pragma unroll
        for (int kc = 0; kc < 8; kc++) {
            uint32_t a[4];
            a[0] = sQ[ ar      * SQ_STR + kc*8 + tig];
            a[1] = sQ[(ar + 8) * SQ_STR + kc*8 + tig];
            a[2] = sQ[ ar      * SQ_STR + kc*8 + 4 + tig];
            a[3] = sQ[(ar + 8) * SQ_STR + kc*8 + 4 + tig];
#pragma unroll
            for (int j = 0; j < 8; j++) {
                uint32_t bfr[2];
                bfr[0] = sK[(j*8 + gid) * SK_STR + kc*8 + tig];
                bfr[1] = sK[(j*8 + gid) * SK_STR + kc*8 + 4 + tig];
                mma_tf32(s_[j], a, bfr);
            }
        }

        float rm0 = -1e30f, rm1 = -1e30f;
#pragma unroll
        for (int j = 0; j < 8; j++) {
            rm0 = fmaxf(rm0, fmaxf(s_[j][0], s_[j][1]));
            rm1 = fmaxf(rm1, fmaxf(s_[j][2], s_[j][3]));
        }
        rm0 = fmaxf(rm0, __shfl_xor_sync(0xffffffffu, rm0, 1));
        rm0 = fmaxf(rm0, __shfl_xor_sync(0xffffffffu, rm0, 2));
        rm1 = fmaxf(rm1, __shfl_xor_sync(0xffffffffu, rm1, 1));
        rm1 = fmaxf(rm1, __shfl_xor_sync(0xffffffffu, rm1, 2));
        float nm0 = fmaxf(m0, rm0), nm1 = fmaxf(m1, rm1);
        float f0 = __expf(m0 - nm0), f1 = __expf(m1 - nm1);
        float rs0 = 0.f, rs1 = 0.f;
#pragma unroll
        for (int j = 0; j < 8; j++) {
            s_[j][0] = __expf(s_[j][0] - nm0);
            s_[j][1] = __expf(s_[j][1] - nm0);
            s_[j][2] = __expf(s_[j][2] - nm1);
            s_[j][3] = __expf(s_[j][3] - nm1);
            rs0 += s_[j][0] + s_[j][1];
            rs1 += s_[j][2] + s_[j][3];
        }
        rs0 += __shfl_xor_sync(0xffffffffu, rs0, 1);
        rs0 += __shfl_xor_sync(0xffffffffu, rs0, 2);
        rs1 += __shfl_xor_sync(0xffffffffu, rs1, 1);
        rs1 += __shfl_xor_sync(0xffffffffu, rs1, 2);
        l0 = l0 * f0 + rs0;
        l1 = l1 * f1 + rs1;
        m0 = nm0; m1 = nm1;
#pragma unroll
        for (int j = 0; j < 16; j++) {
            o[j][0] *= f0; o[j][1] *= f0;
            o[j][2] *= f1; o[j][3] *= f1;
        }

        int srcA = (lane & ~3) | (tig >> 1);
        int srcB = srcA + 2;
        bool odd = (tig & 1);
#pragma unroll
        for (int kc = 0; kc < 8; kc++) {
            float c0 = s_[kc][0], c1 = s_[kc][1], c2 = s_[kc][2], c3 = s_[kc][3];
            float x0 = __shfl_sync(0xffffffffu, c0, srcA);
            float x1 = __shfl_sync(0xffffffffu, c1, srcA);
            float y0 = __shfl_sync(0xffffffffu, c0, srcB);
            float y1 = __shfl_sync(0xffffffffu, c1, srcB);
            float z0 = __shfl_sync(0xffffffffu, c2, srcA);
            float z1 = __shfl_sync(0xffffffffu, c3, srcA);
            float w0 = __shfl_sync(0xffffffffu, c2, srcB);
            float w1 = __shfl_sync(0xffffffffu, c3, srcB);
            uint32_t a[4];
            a[0] = __float_as_uint(odd ? x1 : x0);
            a[1] = __float_as_uint(odd ? z1 : z0);
            a[2] = __float_as_uint(odd ? y1 : y0);
            a[3] = __float_as_uint(odd ? w1 : w0);
#pragma unroll
            for (int j = 0; j < 16; j++) {
                uint32_t bfr[2];
                bfr[0] = sV[(kc*8 +     tig) * SV_STR + j*8 + gid];
                bfr[1] = sV[(kc*8 + 4 + tig) * SV_STR + j*8 + gid];
                mma_tf32(o[j], a, bfr);
            }
        }
    }

    float inv0 = 1.f / l0, inv1 = 1.f / l1;
    int row0 = q0 + wid * 16 + gid, row1 = row0 + 8;
#pragma unroll
    for (int j = 0; j < 16; j++) {
        int col = vcol + j*8 + tig*2;
        *(float2*)&O[(base + row0) * (2*CC) + col] = make_float2(o[j][0]*inv0, o[j][1]*inv0);
        *(float2*)&O[(base + row1) * (2*CC) + col] = make_float2(o[j][2]*inv1, o[j][3]*inv1);
    }
}

// ================= combine: diff + per-head LN(128) + scale (tf32 out) =======
__global__ __launch_bounds__(128) void combine_kernel(
    const float* __restrict__ O1, const float* __restrict__ O2,
    const float* __restrict__ lamp, const float* __restrict__ lnw,
    const float* __restrict__ lnb, float* __restrict__ out)
{
    int row = blockIdx.x, h = blockIdx.y, tid = threadIdx.x;
    size_t idx = (size_t)row * (2*CC) + h * TWO_D + tid;
    float lam = lamp[0];
    float v = O1[idx] - lam * O2[idx];
    float s = v, sq = v * v;
#pragma unroll
    for (int off = 16; off >= 1; off >>= 1) {
        s  += __shfl_xor_sync(0xffffffffu, s,  off);
        sq += __shfl_xor_sync(0xffffffffu, sq, off);
    }
    __shared__ float ws[4], wq[4];
    __shared__ float smu, srs;
    int wid = tid >> 5, lane = tid & 31;
    if (lane == 0) { ws[wid] = s; wq[wid] = sq; }
    __syncthreads();
    if (tid == 0) {
        float S = ws[0]+ws[1]+ws[2]+ws[3];
        float Q = wq[0]+wq[1]+wq[2]+wq[3];
        float mu = S * (1.0f/128.0f);
        float var = Q * (1.0f/128.0f) - mu * mu;
        smu = mu; srs = rsqrtf(var + EPS);
    }
    __syncthreads();
    float y = (v - smu) * srs * lnw[tid] + lnb[tid];
    out[idx] = f2tf32f(y * OUT_SCALE);   // feeds proj GEMM
}

// ================= launch =================
extern "C" void kernel_launch(void* const* d_in, const int* in_sizes, int n_in,
                              void* d_out, int out_size)
{
    const float* x    = (const float*)d_in[0];
    const float* n1w  = (const float*)d_in[1];
    const float* n1b  = (const float*)d_in[2];
    const float* wq   = (const float*)d_in[3];
    const float* wk   = (const float*)d_in[4];
    const float* wv   = (const float*)d_in[5];
    const float* lam  = (const float*)d_in[6];
    const float* alnw = (const float*)d_in[7];
    const float* alnb = (const float*)d_in[8];
    const float* pw   = (const float*)d_in[9];
    const float* pb   = (const float*)d_in[10];
    const float* n2w  = (const float*)d_in[11];
    const float* n2b  = (const float*)d_in[12];
    const float* f1w  = (const float*)d_in[13];
    const float* f1b  = (const float*)d_in[14];
    const float* f2w  = (const float*)d_in[15];
    const float* f2b  = (const float*)d_in[16];
    float* out = (float*)d_out;

    float *xn, *q, *k, *v, *o1, *o2, *att, *xmid, *xn2, *hb;
    float *cwq, *cwk, *cwv, *cpw, *cf1, *cf2;
    cudaGetSymbolAddress((void**)&xn,   g_xn);
    cudaGetSymbolAddress((void**)&q,    g_q);
    cudaGetSymbolAddress((void**)&k,    g_k);
    cudaGetSymbolAddress((void**)&v,    g_v);
    cudaGetSymbolAddress((void**)&o1,   g_o1);
    cudaGetSymbolAddress((void**)&o2,   g_o2);
    cudaGetSymbolAddress((void**)&att,  g_att);
    cudaGetSymbolAddress((void**)&xmid, g_xmid);
    cudaGetSymbolAddress((void**)&xn2,  g_xn2);
    cudaGetSymbolAddress((void**)&hb,   g_h);
    cudaGetSymbolAddress((void**)&cwq,  g_wq);
    cudaGetSymbolAddress((void**)&cwk,  g_wk);
    cudaGetSymbolAddress((void**)&cwv,  g_wv);
    cudaGetSymbolAddress((void**)&cpw,  g_pw);
    cudaGetSymbolAddress((void**)&cf1,  g_f1);
    cudaGetSymbolAddress((void**)&cf2,  g_f2);

    cudaFuncSetAttribute(attn_mma_kernel,
                         cudaFuncAttributeMaxDynamicSharedMemorySize, ATT_SMEM);
    cudaFuncSetAttribute(qkv_gemm,
                         cudaFuncAttributeMaxDynamicSharedMemorySize, GEMM_SMEM_BYTES);
    cudaFuncSetAttribute(tc_gemm<1>,
                         cudaFuncAttributeMaxDynamicSharedMemorySize, GEMM_SMEM_BYTES);
    cudaFuncSetAttribute(tc_gemm<2>,
                         cudaFuncAttributeMaxDynamicSharedMemorySize, GEMM_SMEM_BYTES);

    // 0. weight tf32 pre-conversion (bandwidth-bound, ~25us total)
    {
        int n4a = (2*CC*CC)/4;   // 294912
        int n4b = (4*CC*CC)/4;   // 589824
        cvtw_kernel<<<(n4a+255)/256, 256>>>(wq,  cwq, n4a);
        cvtw_kernel<<<(n4a+255)/256, 256>>>(wk,  cwk, n4a);
        cvtw_kernel<<<(n4a+255)/256, 256>>>(wv,  cwv, n4a);
        cvtw_kernel<<<(n4a+255)/256, 256>>>(pw,  cpw, n4a);
        cvtw_kernel<<<(n4b+255)/256, 256>>>(f1w, cf1, n4b);
        cvtw_kernel<<<(n4b+255)/256, 256>>>(f2w, cf2, n4b);
    }
    // 1. LN1 (tf32-rounded output)
    ln_kernel<<<MROWS, 256>>>(x, n1w, n1b, xn);
    // 2. merged QKV GEMM, one launch, cp.async pipeline
    qkv_gemm<<<dim3(1536/128, MROWS/128, 3), 256, GEMM_SMEM_BYTES>>>(xn, cwq, cwk, cwv, q, k, v);
    // 3. flash attention per split on tensor cores
    attn_mma_kernel<<<dim3(NN/128, HH, BB*2), 256, ATT_SMEM>>>(q, k, v, o1, o2);
    // 3b. combine: diff + head-LN + scale (tf32-rounded output)
    combine_kernel<<<dim3(MROWS, HH), 128>>>(o1, o2, lam, alnw, alnb, att);
    // 4. proj + bias + residual (4096 x 768 x 1536)
    tc_gemm<1><<<dim3(768/128, MROWS/128), 256, GEMM_SMEM_BYTES>>>(att, cpw, pb, x, xmid, MROWS, 768, 1536);
    // 5. LN2 (tf32-rounded output)
    ln_kernel<<<MROWS, 256>>>(xmid, n2w, n2b, xn2);
    // 6. fc1 + bias + GELU (4096 x 3072 x 768), tf32-rounded output
    tc_gemm<2><<<dim3(3072/128, MROWS/128), 256, GEMM_SMEM_BYTES>>>(xn2, cf1, f1b, nullptr, hb, MROWS, 3072, 768);
    // 7. fc2 + bias + residual (4096 x 768 x 3072), full f32 output
    tc_gemm<1><<<dim3(768/128, MROWS/128), 256, GEMM_SMEM_BYTES>>>(hb, cf2, f2b, xmid, out, MROWS, 768, 3072);
}

// round 10
// speedup vs baseline: 1.8981x; 1.7630x over previous
#include <cuda_runtime.h>
#include <cuda_fp16.h>
#include <math.h>
#include <stdint.h>

// ---------------- problem constants ----------------
#define BB 4
#define NN 1024
#define CC 768
#define HH 12
#define TWO_D 128
#define MROWS (BB*NN)    // 4096
#define SCALE 0.125f     // D^-0.5
#define EPS 1e-5f
#define OUT_SCALE 0.8f   // 1 - LAMBDA_INIT

// ---------------- scratch (device globals; no alloc allowed) ----------------
__device__ __half g_xn  [MROWS*CC];
__device__ __half g_q   [MROWS*2*CC];
__device__ __half g_k   [MROWS*2*CC];
__device__ __half g_v   [MROWS*2*CC];
__device__ float  g_o1  [MROWS*2*CC];
__device__ float  g_o2  [MROWS*2*CC];
__device__ __half g_att [MROWS*2*CC];
__device__ float  g_xmid[MROWS*CC];
__device__ __half g_xn2 [MROWS*CC];
__device__ __half g_h   [MROWS*4*CC];
// converted fp16 weights
__device__ __half g_wq [2*CC*CC];
__device__ __half g_wk [2*CC*CC];
__device__ __half g_wv [2*CC*CC];
__device__ __half g_pw [CC*2*CC];
__device__ __half g_f1 [4*CC*CC];
__device__ __half g_f2 [CC*4*CC];

// ================= helpers =================
__device__ __forceinline__ uint32_t f22h2(float a, float b) {
    __half2 h = __floats2half2_rn(a, b);
    return *reinterpret_cast<uint32_t*>(&h);
}
__device__ __forceinline__ void mma_fp16(float* c, const uint32_t* a, const uint32_t* b) {
    asm volatile("mma.sync.aligned.m16n8k16.row.col.f32.f16.f16.f32 "
        "{%0,%1,%2,%3}, {%4,%5,%6,%7}, {%8,%9}, {%0,%1,%2,%3};"
        : "+f"(c[0]), "+f"(c[1]), "+f"(c[2]), "+f"(c[3])
        : "r"(a[0]), "r"(a[1]), "r"(a[2]), "r"(a[3]), "r"(b[0]), "r"(b[1]));
}
__device__ __forceinline__ void ldsm_x2_trans(uint32_t& r0, uint32_t& r1, uint32_t addr) {
    asm volatile("ldmatrix.sync.aligned.m8n8.x2.trans.shared.b16 {%0,%1}, [%2];"
        : "=r"(r0), "=r"(r1) : "r"(addr));
}
__device__ __forceinline__ uint32_t smem_u32(const void* p) {
    uint32_t a;
    asm("{ .reg .u64 t; cvta.to.shared.u64 t, %1; cvt.u32.u64 %0, t; }" : "=r"(a) : "l"(p));
    return a;
}
__device__ __forceinline__ void cp16(uint32_t dst, const void* src) {
    asm volatile("cp.async.ca.shared.global [%0], [%1], 16;" :: "r"(dst), "l"(src));
}
__device__ __forceinline__ void cp_commit() {
    asm volatile("cp.async.commit_group;" ::: "memory");
}
__device__ __forceinline__ void cp_wait1() {
    asm volatile("cp.async.wait_group 1;" ::: "memory");
}

// ================= weight fp16 pre-conversion =================
__global__ __launch_bounds__(256) void cvtw_kernel(
    const float* __restrict__ s, __half* __restrict__ d, int n4)
{
    int i = blockIdx.x * 256 + threadIdx.x;
    if (i < n4) {
        float4 v = ((const float4*)s)[i];
        __half2* dp = (__half2*)d;
        dp[i*2 + 0] = __floats2half2_rn(v.x, v.y);
        dp[i*2 + 1] = __floats2half2_rn(v.z, v.w);
    }
}

// ================= LayerNorm over 768 (fp16 output) =================
__global__ __launch_bounds__(256) void ln_kernel(
    const float* __restrict__ x, const float* __restrict__ w,
    const float* __restrict__ b, __half* __restrict__ out)
{
    int row = blockIdx.x;
    int tid = threadIdx.x;
    const float* xr = x + (size_t)row * CC;
    float v0 = xr[tid], v1 = xr[tid + 256], v2 = xr[tid + 512];
    float s  = v0 + v1 + v2;
    float sq = v0*v0 + v1*v1 + v2*v2;
#pragma unroll
    for (int off = 16; off >= 1; off >>= 1) {
        s  += __shfl_xor_sync(0xffffffffu, s,  off);
        sq += __shfl_xor_sync(0xffffffffu, sq, off);
    }
    __shared__ float rs_[8], rq_[8];
    __shared__ float smu, srs;
    int wid = tid >> 5, lane = tid & 31;
    if (lane == 0) { rs_[wid] = s; rq_[wid] = sq; }
    __syncthreads();
    if (tid == 0) {
        float S = 0.f, Q = 0.f;
#pragma unroll
        for (int i = 0; i < 8; i++) { S += rs_[i]; Q += rq_[i]; }
        float mu = S / (float)CC;
        float var = Q / (float)CC - mu * mu;
        smu = mu; srs = rsqrtf(var + EPS);
    }
    __syncthreads();
    float mu = smu, r = srs;
    __half* orow = out + (size_t)row * CC;
    orow[tid]       = __float2half_rn((v0 - mu) * r * w[tid]       + b[tid]);
    orow[tid + 256] = __float2half_rn((v1 - mu) * r * w[tid + 256] + b[tid + 256]);
    orow[tid + 512] = __float2half_rn((v2 - mu) * r * w[tid + 512] + b[tid + 512]);
}

// ================= FP16 mma.sync GEMM, cp.async 3-stage pipeline =============
// C = A(MxK) * B(NxK)^T. 128x128 tile, 8 warps (2m x 4n), 64x32 warp tile.
// KC=64 halves per chunk; smem rows stride 72 halves (bank-conflict-free).
// EPI 0: half out   1: +bias+residual, f32 out   2: +bias+GELU, half out
#define KC 64
#define STR_H 72
#define STAGE_H (128 * STR_H)          // halves per matrix per stage
#define STAGE_BYTES (STAGE_H * 2)      // 18432
#define GSTAGES 3
#define GEMM_SMEM_BYTES (GSTAGES * 2 * STAGE_BYTES)  // 110592

template<int EPI>
__device__ __forceinline__ void gemm_body(
    const __half* __restrict__ A, const __half* __restrict__ B,
    const float* __restrict__ bias, const float* __restrict__ res,
    void* __restrict__ Cp, int M, int N, int K, int bx, int by)
{
    extern __shared__ __half gsmh[];
    uint32_t sb = smem_u32(gsmh);

    int tid  = threadIdx.x;
    int wid  = tid >> 5;
    int lane = tid & 31;
    int wm = wid >> 2;
    int wn = wid & 3;
    int gid = lane >> 2;
    int tig = lane & 3;

    int m0 = by * 128, n0 = bx * 128;
    int seg = tid & 7;     // 16B segment within 128B row
    int r0  = tid >> 3;    // 0..31

    float acc[4][4][4];
#pragma unroll
    for (int i = 0; i < 4; i++)
#pragma unroll
        for (int j = 0; j < 4; j++)
#pragma unroll
            for (int r = 0; r < 4; r++) acc[i][j][r] = 0.f;

    int Cn = K / KC;

    auto issue = [&](int c) {
        int s = c % GSTAGES;
        uint32_t abase = sb + (uint32_t)s * 2u * STAGE_BYTES;
        uint32_t bbase = abase + STAGE_BYTES;
        int k0 = c * KC;
#pragma unroll
        for (int p = 0; p < 4; p++) {
            int r = r0 + p * 32;
            uint32_t soff = (uint32_t)(r * STR_H + seg * 8) * 2u;
            cp16(abase + soff, A + (size_t)(m0 + r) * K + k0 + seg * 8);
            cp16(bbase + soff, B + (size_t)(n0 + r) * K + k0 + seg * 8);
        }
    };

    issue(0); cp_commit();
    issue(1); cp_commit();

    for (int c = 0; c < Cn; c++) {
        cp_wait1();
        __syncthreads();
        if (c + 2 < Cn) issue(c + 2);
        cp_commit();

        const __half* As = gsmh + (size_t)(c % GSTAGES) * 2u * STAGE_H;
        const __half* Bs = As + STAGE_H;
#pragma unroll
        for (int ks = 0; ks < 4; ks++) {
            int k0 = ks * 16;
            uint32_t afr[4][4], bfr[4][2];
#pragma unroll
            for (int i = 0; i < 4; i++) {
                int rb = wm * 64 + i * 16;
                afr[i][0] = *(const uint32_t*)&As[(rb + gid    ) * STR_H + k0 + tig*2];
                afr[i][1] = *(const uint32_t*)&As[(rb + 8 + gid) * STR_H + k0 + tig*2];
                afr[i][2] = *(const uint32_t*)&As[(rb + gid    ) * STR_H + k0 + 8 + tig*2];
                afr[i][3] = *(const uint32_t*)&As[(rb + 8 + gid) * STR_H + k0 + 8 + tig*2];
            }
#pragma unroll
            for (int j = 0; j < 4; j++) {
                int cb = wn * 32 + j * 8;
                bfr[j][0] = *(const uint32_t*)&Bs[(cb + gid) * STR_H + k0 + tig*2];
                bfr[j][1] = *(const uint32_t*)&Bs[(cb + gid) * STR_H + k0 + 8 + tig*2];
            }
#pragma unroll
            for (int i = 0; i < 4; i++)
#pragma unroll
                for (int j = 0; j < 4; j++)
                    mma_fp16(acc[i][j], afr[i], bfr[j]);
        }
    }

#pragma unroll
    for (int i = 0; i < 4; i++) {
#pragma unroll
        for (int j = 0; j < 4; j++) {
            int col = n0 + wn * 32 + j * 8 + tig * 2;
#pragma unroll
            for (int half_ = 0; half_ < 2; half_++) {
                int row = m0 + wm * 64 + i * 16 + gid + half_ * 8;
                float vx = acc[i][j][half_ * 2 + 0];
                float vy = acc[i][j][half_ * 2 + 1];
                if (EPI == 0) {
                    __half* Ch = (__half*)Cp;
                    *(__half2*)&Ch[(size_t)row * N + col] = __floats2half2_rn(vx, vy);
                } else if (EPI == 1) {
                    const float* rrow = res + (size_t)row * N + col;
                    vx += bias[col]     + rrow[0];
                    vy += bias[col + 1] + rrow[1];
                    *(float2*)((float*)Cp + (size_t)row * N + col) = make_float2(vx, vy);
                } else {
                    vx += bias[col];
                    vy += bias[col + 1];
                    vx = 0.5f * vx * (1.0f + erff(vx * 0.70710678118654752f));
                    vy = 0.5f * vy * (1.0f + erff(vy * 0.70710678118654752f));
                    __half* Ch = (__half*)Cp;
                    *(__half2*)&Ch[(size_t)row * N + col] = __floats2half2_rn(vx, vy);
                }
            }
        }
    }
}

template<int EPI>
__global__ __launch_bounds__(256, 1) void tc_gemm(
    const __half* __restrict__ A, const __half* __restrict__ B,
    const float* __restrict__ bias, const float* __restrict__ res,
    void* __restrict__ C, int M, int N, int K)
{
    gemm_body<EPI>(A, B, bias, res, C, M, N, K, blockIdx.x, blockIdx.y);
}

// Merged QKV: one launch, z selects weight/output.
__global__ __launch_bounds__(256, 1) void qkv_gemm(
    const __half* __restrict__ A,
    const __half* __restrict__ Wq, const __half* __restrict__ Wk, const __half* __restrict__ Wv,
    __half* __restrict__ Oq, __half* __restrict__ Ok, __half* __restrict__ Ov)
{
    const __half* B;
    __half* C;
    int z = blockIdx.z;
    if (z == 0)      { B = Wq; C = Oq; }
    else if (z == 1) { B = Wk; C = Ok; }
    else             { B = Wv; C = Ov; }
    gemm_body<0>(A, B, nullptr, nullptr, (void*)C, MROWS, 2*CC, CC, blockIdx.x, blockIdx.y);
}

// ================= Flash attention (fp16 mma, one split per block) ===========
// grid (8, 12, 8): x=q-tile(128 rows), y=head, z=b*2+split. 8 warps x 16 rows.
#define SQS 72
#define SKS 72
#define SVS 136
#define SQ_H (128*SQS)
#define SK_H (64*SKS)
#define SV_H (64*SVS)
#define ATT_SMEM ((SQ_H+SK_H+SV_H)*2)   // 45056 bytes

__global__ __launch_bounds__(256, 2) void attn_mma_kernel(
    const __half* __restrict__ Q, const __half* __restrict__ K,
    const __half* __restrict__ Vv, float* __restrict__ O1, float* __restrict__ O2)
{
    extern __shared__ __half ash[];
    __half* sQh = ash;
    __half* sKh = ash + SQ_H;
    __half* sVh = ash + SQ_H + SK_H;
    uint32_t sv_base = smem_u32(sVh);

    int tid  = threadIdx.x;
    int wid  = tid >> 5;
    int lane = tid & 31;
    int gid  = lane >> 2;
    int tig  = lane & 3;

    int q0 = blockIdx.x * 128;
    int h  = blockIdx.y;
    int bz = blockIdx.z;
    int b  = bz >> 1, sp = bz & 1;
    size_t base = (size_t)b * NN;
    int qkcol = h * TWO_D + sp * 64;
    int vcol  = h * TWO_D;
    float* O = sp ? O2 : O1;

    // stage Q (x SCALE; exact in fp16 since 0.125 is a power of two)
    {
        int seg = tid & 7, r0 = tid >> 3;
        __half2 smul = __float2half2_rn(SCALE);
#pragma unroll
        for (int p = 0; p < 4; p++) {
            int r = r0 + p * 32;
            float4 qv = *(const float4*)&Q[(base + q0 + r) * (2*CC) + qkcol + seg * 8];
            __half2* qh = (__half2*)&qv;
            qh[0] = __hmul2(qh[0], smul); qh[1] = __hmul2(qh[1], smul);
            qh[2] = __hmul2(qh[2], smul); qh[3] = __hmul2(qh[3], smul);
            *(float4*)&sQh[r * SQS + seg * 8] = qv;
        }
    }

    float o[16][4];
#pragma unroll
    for (int j = 0; j < 16; j++)
#pragma unroll
        for (int r = 0; r < 4; r++) o[j][r] = 0.f;
    float m0 = -1e30f, m1 = -1e30f, l0 = 0.f, l1 = 0.f;

    for (int t = 0; t < NN / 64; t++) {
        __syncthreads();
        // stage K (64x64) and V (64x128)
        {
            int seg = tid & 7, r0 = tid >> 3;
#pragma unroll
            for (int p = 0; p < 2; p++) {
                int r = r0 + p * 32;
                float4 kv = *(const float4*)&K[(base + t*64 + r) * (2*CC) + qkcol + seg * 8];
                *(float4*)&sKh[r * SKS + seg * 8] = kv;
            }
            int seg16 = tid & 15, r0v = tid >> 4;
#pragma unroll
            for (int p = 0; p < 4; p++) {
                int r = r0v + p * 16;
                float4 vv = *(const float4*)&Vv[(base + t*64 + r) * (2*CC) + vcol + seg16 * 8];
                *(float4*)&sVh[r * SVS + seg16 * 8] = vv;
            }
        }
        __syncthreads();

        // S = Q K^T (16 rows x 64 keys per warp), 4 k16 steps over 64 dims
        float s_[8][4];
#pragma unroll
        for (int j = 0; j < 8; j++)
#pragma unroll
            for (int r = 0; r < 4; r++) s_[j][r] = 0.f;
        int ar = wid * 16 + gid;
#pragma unroll
        for (int ks = 0; ks < 4; ks++) {
            int k0 = ks * 16;
            uint32_t a[4];
            a[0] = *(const uint32_t*)&sQh[ ar      * SQS + k0 + tig*2];
            a[1] = *(const uint32_t*)&sQh[(ar + 8) * SQS + k0 + tig*2];
            a[2] = *(const uint32_t*)&sQh[ ar      * SQS + k0 + 8 + tig*2];
            a[3] = *(const uint32_t*)&sQh[(ar + 8) * SQS + k0 + 8 + tig*2];
#pragma unroll
            for (int j = 0; j < 8; j++) {
                uint32_t bfr[2];
                bfr[0] = *(const uint32_t*)&sKh[(j*8 + gid) * SKS + k0 + tig*2];
                bfr[1] = *(const uint32_t*)&sKh[(j*8 + gid) * SKS + k0 + 8 + tig*2];
                mma_fp16(s_[j], a, bfr);
            }
        }

        // online softmax (rows gid and gid+8)
        float rm0 = -1e30f, rm1 = -1e30f;
#pragma unroll
        for (int j = 0; j < 8; j++) {
            rm0 = fmaxf(rm0, fmaxf(s_[j][0], s_[j][1]));
            rm1 = fmaxf(rm1, fmaxf(s_[j][2], s_[j][3]));
        }
        rm0 = fmaxf(rm0, __shfl_xor_sync(0xffffffffu, rm0, 1));
        rm0 = fmaxf(rm0, __shfl_xor_sync(0xffffffffu, rm0, 2));
        rm1 = fmaxf(rm1, __shfl_xor_sync(0xffffffffu, rm1, 1));
        rm1 = fmaxf(rm1, __shfl_xor_sync(0xffffffffu, rm1, 2));
        float nm0 = fmaxf(m0, rm0), nm1 = fmaxf(m1, rm1);
        float f0 = __expf(m0 - nm0), f1 = __expf(m1 - nm1);
        float rs0 = 0.f, rs1 = 0.f;
#pragma unroll
        for (int j = 0; j < 8; j++) {
            s_[j][0] = __expf(s_[j][0] - nm0);
            s_[j][1] = __expf(s_[j][1] - nm0);
            s_[j][2] = __expf(s_[j][2] - nm1);
            s_[j][3] = __expf(s_[j][3] - nm1);
            rs0 += s_[j][0] + s_[j][1];
            rs1 += s_[j][2] + s_[j][3];
        }
        rs0 += __shfl_xor_sync(0xffffffffu, rs0, 1);
        rs0 += __shfl_xor_sync(0xffffffffu, rs0, 2);
        rs1 += __shfl_xor_sync(0xffffffffu, rs1, 1);
        rs1 += __shfl_xor_sync(0xffffffffu, rs1, 2);
        l0 = l0 * f0 + rs0;
        l1 = l1 * f1 + rs1;
        m0 = nm0; m1 = nm1;
#pragma unroll
        for (int j = 0; j < 16; j++) {
            o[j][0] *= f0; o[j][1] *= f0;
            o[j][2] *= f1; o[j][3] *= f1;
        }

        // O += P @ V : fp16 P C-fragment IS the A-fragment (no shuffles).
        // V B-fragments via ldmatrix.x2.trans from [key][dim] tile.
#pragma unroll
        for (int kc = 0; kc < 4; kc++) {
            uint32_t a[4];
            a[0] = f22h2(s_[2*kc  ][0], s_[2*kc  ][1]);
            a[1] = f22h2(s_[2*kc  ][2], s_[2*kc  ][3]);
            a[2] = f22h2(s_[2*kc+1][0], s_[2*kc+1][1]);
            a[3] = f22h2(s_[2*kc+1][2], s_[2*kc+1][3]);
            uint32_t rowaddr = sv_base + (uint32_t)((kc*16 + (lane & 15)) * SVS) * 2u;
#pragma unroll
            for (int j = 0; j < 16; j++) {
                uint32_t b0, b1;
                ldsm_x2_trans(b0, b1, rowaddr + j * 16);
                uint32_t bfr[2] = {b0, b1};
                mma_fp16(o[j], a, bfr);
            }
        }
    }

    // epilogue: normalize, store split output (f32)
    float inv0 = 1.f / l0, inv1 = 1.f / l1;
    int row0 = q0 + wid * 16 + gid, row1 = row0 + 8;
#pragma unroll
    for (int j = 0; j < 16; j++) {
        int col = vcol + j*8 + tig*2;
        *(float2*)&O[(base + row0) * (2*CC) + col] = make_float2(o[j][0]*inv0, o[j][1]*inv0);
        *(float2*)&O[(base + row1) * (2*CC) + col] = make_float2(o[j][2]*inv1, o[j][3]*inv1);
    }
}

// ================= combine: diff + per-head LN(128) + scale (fp16 out) =======
__global__ __launch_bounds__(128) void combine_kernel(
    const float* __restrict__ O1, const float* __restrict__ O2,
    const float* __restrict__ lamp, const float* __restrict__ lnw,
    const float* __restrict__ lnb, __half* __restrict__ out)
{
    int row = blockIdx.x, h = blockIdx.y, tid = threadIdx.x;
    size_t idx = (size_t)row * (2*CC) + h * TWO_D + tid;
    float lam = lamp[0];
    float v = O1[idx] - lam * O2[idx];
    float s = v, sq = v * v;
#pragma unroll
    for (int off = 16; off >= 1; off >>= 1) {
        s  += __shfl_xor_sync(0xffffffffu, s,  off);
        sq += __shfl_xor_sync(0xffffffffu, sq, off);
    }
    __shared__ float ws[4], wq[4];
    __shared__ float smu, srs;
    int wid = tid >> 5, lane = tid & 31;
    if (lane == 0) { ws[wid] = s; wq[wid] = sq; }
    __syncthreads();
    if (tid == 0) {
        float S = ws[0]+ws[1]+ws[2]+ws[3];
        float Q = wq[0]+wq[1]+wq[2]+wq[3];
        float mu = S * (1.0f/128.0f);
        float var = Q * (1.0f/128.0f) - mu * mu;
        smu = mu; srs = rsqrtf(var + EPS);
    }
    __syncthreads();
    float y = (v - smu) * srs * lnw[tid] + lnb[tid];
    out[idx] = __float2half_rn(y * OUT_SCALE);
}

// ================= launch =================
extern "C" void kernel_launch(void* const* d_in, const int* in_sizes, int n_in,
                              void* d_out, int out_size)
{
    const float* x    = (const float*)d_in[0];
    const float* n1w  = (const float*)d_in[1];
    const float* n1b  = (const float*)d_in[2];
    const float* wq   = (const float*)d_in[3];
    const float* wk   = (const float*)d_in[4];
    const float* wv   = (const float*)d_in[5];
    const float* lam  = (const float*)d_in[6];
    const float* alnw = (const float*)d_in[7];
    const float* alnb = (const float*)d_in[8];
    const float* pw   = (const float*)d_in[9];
    const float* pb   = (const float*)d_in[10];
    const float* n2w  = (const float*)d_in[11];
    const float* n2b  = (const float*)d_in[12];
    const float* f1w  = (const float*)d_in[13];
    const float* f1b  = (const float*)d_in[14];
    const float* f2w  = (const float*)d_in[15];
    const float* f2b  = (const float*)d_in[16];
    float* out = (float*)d_out;

    __half *xn, *q, *k, *v, *att, *xn2, *hb;
    float *o1, *o2, *xmid;
    __half *cwq, *cwk, *cwv, *cpw, *cf1, *cf2;
    cudaGetSymbolAddress((void**)&xn,   g_xn);
    cudaGetSymbolAddress((void**)&q,    g_q);
    cudaGetSymbolAddress((void**)&k,    g_k);
    cudaGetSymbolAddress((void**)&v,    g_v);
    cudaGetSymbolAddress((void**)&o1,   g_o1);
    cudaGetSymbolAddress((void**)&o2,   g_o2);
    cudaGetSymbolAddress((void**)&att,  g_att);
    cudaGetSymbolAddress((void**)&xmid, g_xmid);
    cudaGetSymbolAddress((void**)&xn2,  g_xn2);
    cudaGetSymbolAddress((void**)&hb,   g_h);
    cudaGetSymbolAddress((void**)&cwq,  g_wq);
    cudaGetSymbolAddress((void**)&cwk,  g_wk);
    cudaGetSymbolAddress((void**)&cwv,  g_wv);
    cudaGetSymbolAddress((void**)&cpw,  g_pw);
    cudaGetSymbolAddress((void**)&cf1,  g_f1);
    cudaGetSymbolAddress((void**)&cf2,  g_f2);

    cudaFuncSetAttribute(attn_mma_kernel,
                         cudaFuncAttributeMaxDynamicSharedMemorySize, ATT_SMEM);
    cudaFuncSetAttribute(qkv_gemm,
                         cudaFuncAttributeMaxDynamicSharedMemorySize, GEMM_SMEM_BYTES);
    cudaFuncSetAttribute(tc_gemm<1>,
                         cudaFuncAttributeMaxDynamicSharedMemorySize, GEMM_SMEM_BYTES);
    cudaFuncSetAttribute(tc_gemm<2>,
                         cudaFuncAttributeMaxDynamicSharedMemorySize, GEMM_SMEM_BYTES);

    // 0. weight fp16 pre-conversion (bandwidth-bound)
    {
        int n4a = (2*CC*CC)/4;
        int n4b = (4*CC*CC)/4;
        cvtw_kernel<<<(n4a+255)/256, 256>>>(wq,  cwq, n4a);
        cvtw_kernel<<<(n4a+255)/256, 256>>>(wk,  cwk, n4a);
        cvtw_kernel<<<(n4a+255)/256, 256>>>(wv,  cwv, n4a);
        cvtw_kernel<<<(n4a+255)/256, 256>>>(pw,  cpw, n4a);
        cvtw_kernel<<<(n4b+255)/256, 256>>>(f1w, cf1, n4b);
        cvtw_kernel<<<(n4b+255)/256, 256>>>(f2w, cf2, n4b);
    }
    // 1. LN1 (fp16 output)
    ln_kernel<<<MROWS, 256>>>(x, n1w, n1b, xn);
    // 2. merged QKV GEMM (fp16), one launch
    qkv_gemm<<<dim3(1536/128, MROWS/128, 3), 256, GEMM_SMEM_BYTES>>>(xn, cwq, cwk, cwv, q, k, v);
    // 3. flash attention per split (fp16 mma)
    attn_mma_kernel<<<dim3(NN/128, HH, BB*2), 256, ATT_SMEM>>>(q, k, v, o1, o2);
    // 3b. combine: diff + head-LN + scale (fp16 output)
    combine_kernel<<<dim3(MROWS, HH), 128>>>(o1, o2, lam, alnw, alnb, att);
    // 4. proj + bias + residual (f32 out)
    tc_gemm<1><<<dim3(768/128, MROWS/128), 256, GEMM_SMEM_BYTES>>>(att, cpw, pb, x, xmid, MROWS, 768, 1536);
    // 5. LN2 (fp16 output)
    ln_kernel<<<MROWS, 256>>>(xmid, n2w, n2b, xn2);
    // 6. fc1 + bias + GELU (fp16 out)
    tc_gemm<2><<<dim3(3072/128, MROWS/128), 256, GEMM_SMEM_BYTES>>>(xn2, cf1, f1b, nullptr, hb, MROWS, 3072, 768);
    // 7. fc2 + bias + residual (f32 out)
    tc_gemm<1><<<dim3(768/128, MROWS/128), 256, GEMM_SMEM_BYTES>>>(hb, cf2, f2b, xmid, out, MROWS, 768, 3072);
}

// round 11
// speedup vs baseline: 2.0041x; 1.0558x over previous
#include <cuda_runtime.h>
#include <cuda_fp16.h>
#include <math.h>
#include <stdint.h>

// ---------------- problem constants ----------------
#define BB 4
#define NN 1024
#define CC 768
#define HH 12
#define TWO_D 128
#define MROWS (BB*NN)    // 4096
#define SCALE 0.125f     // D^-0.5
#define EPS 1e-5f
#define OUT_SCALE 0.8f   // 1 - LAMBDA_INIT

// ---------------- scratch (device globals; no alloc allowed) ----------------
__device__ __half g_xn  [MROWS*CC];
__device__ __half g_q   [MROWS*2*CC];
__device__ __half g_k   [MROWS*2*CC];
__device__ __half g_v   [MROWS*2*CC];
__device__ __half g_att [MROWS*2*CC];
__device__ float  g_xmid[MROWS*CC];
__device__ __half g_xn2 [MROWS*CC];
__device__ __half g_h   [MROWS*4*CC];
// converted fp16 weights
__device__ __half g_wq [2*CC*CC];
__device__ __half g_wk [2*CC*CC];
__device__ __half g_wv [2*CC*CC];
__device__ __half g_pw [CC*2*CC];
__device__ __half g_f1 [4*CC*CC];
__device__ __half g_f2 [CC*4*CC];

// ================= helpers =================
__device__ __forceinline__ uint32_t f22h2(float a, float b) {
    __half2 h = __floats2half2_rn(a, b);
    return *reinterpret_cast<uint32_t*>(&h);
}
__device__ __forceinline__ void mma_fp16(float* c, const uint32_t* a, const uint32_t* b) {
    asm volatile("mma.sync.aligned.m16n8k16.row.col.f32.f16.f16.f32 "
        "{%0,%1,%2,%3}, {%4,%5,%6,%7}, {%8,%9}, {%0,%1,%2,%3};"
        : "+f"(c[0]), "+f"(c[1]), "+f"(c[2]), "+f"(c[3])
        : "r"(a[0]), "r"(a[1]), "r"(a[2]), "r"(a[3]), "r"(b[0]), "r"(b[1]));
}
__device__ __forceinline__ void ldsm_x4(uint32_t* r, uint32_t addr) {
    asm volatile("ldmatrix.sync.aligned.m8n8.x4.shared.b16 {%0,%1,%2,%3}, [%4];"
        : "=r"(r[0]), "=r"(r[1]), "=r"(r[2]), "=r"(r[3]) : "r"(addr));
}
__device__ __forceinline__ void ldsm_x2(uint32_t* r, uint32_t addr) {
    asm volatile("ldmatrix.sync.aligned.m8n8.x2.shared.b16 {%0,%1}, [%2];"
        : "=r"(r[0]), "=r"(r[1]) : "r"(addr));
}
__device__ __forceinline__ void ldsm_x2_trans(uint32_t& r0, uint32_t& r1, uint32_t addr) {
    asm volatile("ldmatrix.sync.aligned.m8n8.x2.trans.shared.b16 {%0,%1}, [%2];"
        : "=r"(r0), "=r"(r1) : "r"(addr));
}
__device__ __forceinline__ uint32_t smem_u32(const void* p) {
    uint32_t a;
    asm("{ .reg .u64 t; cvta.to.shared.u64 t, %1; cvt.u32.u64 %0, t; }" : "=r"(a) : "l"(p));
    return a;
}
__device__ __forceinline__ void cp16(uint32_t dst, const void* src) {
    asm volatile("cp.async.ca.shared.global [%0], [%1], 16;" :: "r"(dst), "l"(src));
}
__device__ __forceinline__ void cp_commit() {
    asm volatile("cp.async.commit_group;" ::: "memory");
}
__device__ __forceinline__ void cp_wait1() {
    asm volatile("cp.async.wait_group 1;" ::: "memory");
}

// ================= weight fp16 pre-conversion =================
__global__ __launch_bounds__(256) void cvtw_kernel(
    const float* __restrict__ s, __half* __restrict__ d, int n4)
{
    int i = blockIdx.x * 256 + threadIdx.x;
    if (i < n4) {
        float4 v = ((const float4*)s)[i];
        __half2* dp = (__half2*)d;
        dp[i*2 + 0] = __floats2half2_rn(v.x, v.y);
        dp[i*2 + 1] = __floats2half2_rn(v.z, v.w);
    }
}

// ================= LayerNorm over 768 (fp16 output) =================
__global__ __launch_bounds__(256) void ln_kernel(
    const float* __restrict__ x, const float* __restrict__ w,
    const float* __restrict__ b, __half* __restrict__ out)
{
    int row = blockIdx.x;
    int tid = threadIdx.x;
    const float* xr = x + (size_t)row * CC;
    float v0 = xr[tid], v1 = xr[tid + 256], v2 = xr[tid + 512];
    float s  = v0 + v1 + v2;
    float sq = v0*v0 + v1*v1 + v2*v2;
#pragma unroll
    for (int off = 16; off >= 1; off >>= 1) {
        s  += __shfl_xor_sync(0xffffffffu, s,  off);
        sq += __shfl_xor_sync(0xffffffffu, sq, off);
    }
    __shared__ float rs_[8], rq_[8];
    __shared__ float smu, srs;
    int wid = tid >> 5, lane = tid & 31;
    if (lane == 0) { rs_[wid] = s; rq_[wid] = sq; }
    __syncthreads();
    if (tid == 0) {
        float S = 0.f, Q = 0.f;
#pragma unroll
        for (int i = 0; i < 8; i++) { S += rs_[i]; Q += rq_[i]; }
        float mu = S / (float)CC;
        float var = Q / (float)CC - mu * mu;
        smu = mu; srs = rsqrtf(var + EPS);
    }
    __syncthreads();
    float mu = smu, r = srs;
    __half* orow = out + (size_t)row * CC;
    orow[tid]       = __float2half_rn((v0 - mu) * r * w[tid]       + b[tid]);
    orow[tid + 256] = __float2half_rn((v1 - mu) * r * w[tid + 256] + b[tid + 256]);
    orow[tid + 512] = __float2half_rn((v2 - mu) * r * w[tid + 512] + b[tid + 512]);
}

// ================= FP16 mma.sync GEMM, cp.async pipeline + ldmatrix ==========
#define KC 64
#define STR_H 72
#define STAGE_H (128 * STR_H)
#define STAGE_BYTES (STAGE_H * 2)
#define GSTAGES 3
#define GEMM_SMEM_BYTES (GSTAGES * 2 * STAGE_BYTES)  // 110592

template<int EPI>
__device__ __forceinline__ void gemm_body(
    const __half* __restrict__ A, const __half* __restrict__ B,
    const float* __restrict__ bias, const float* __restrict__ res,
    void* __restrict__ Cp, int M, int N, int K, int bx, int by)
{
    extern __shared__ __half gsmh[];
    uint32_t sb = smem_u32(gsmh);

    int tid  = threadIdx.x;
    int wid  = tid >> 5;
    int lane = tid & 31;
    int wm = wid >> 2;
    int wn = wid & 3;
    int gid = lane >> 2;
    int tig = lane & 3;

    int m0 = by * 128, n0 = bx * 128;
    int seg = tid & 7;
    int r0  = tid >> 3;

    // ldmatrix lane-address offsets (in bytes)
    uint32_t a_off = (uint32_t)((lane & 15) * STR_H + (lane >> 4) * 8) * 2u;
    uint32_t b_off = (uint32_t)((lane & 7) * STR_H + ((lane >> 3) & 1) * 8) * 2u;

    float acc[4][4][4];
#pragma unroll
    for (int i = 0; i < 4; i++)
#pragma unroll
        for (int j = 0; j < 4; j++)
#pragma unroll
            for (int r = 0; r < 4; r++) acc[i][j][r] = 0.f;

    int Cn = K / KC;

    auto issue = [&](int c) {
        int s = c % GSTAGES;
        uint32_t abase = sb + (uint32_t)s * 2u * STAGE_BYTES;
        uint32_t bbase = abase + STAGE_BYTES;
        int k0 = c * KC;
#pragma unroll
        for (int p = 0; p < 4; p++) {
            int r = r0 + p * 32;
            uint32_t soff = (uint32_t)(r * STR_H + seg * 8) * 2u;
            cp16(abase + soff, A + (size_t)(m0 + r) * K + k0 + seg * 8);
            cp16(bbase + soff, B + (size_t)(n0 + r) * K + k0 + seg * 8);
        }
    };

    issue(0); cp_commit();
    issue(1); cp_commit();

    for (int c = 0; c < Cn; c++) {
        cp_wait1();
        __syncthreads();
        if (c + 2 < Cn) issue(c + 2);
        cp_commit();

        uint32_t As_u = sb + (uint32_t)(c % GSTAGES) * 2u * STAGE_BYTES;
        uint32_t Bs_u = As_u + STAGE_BYTES;
#pragma unroll
        for (int ks = 0; ks < 4; ks++) {
            int k0 = ks * 16;
            uint32_t afr[4][4], bfr[4][2];
#pragma unroll
            for (int i = 0; i < 4; i++) {
                int rb = wm * 64 + i * 16;
                ldsm_x4(afr[i], As_u + (uint32_t)(rb * STR_H + k0) * 2u + a_off);
            }
#pragma unroll
            for (int j = 0; j < 4; j++) {
                int cb = wn * 32 + j * 8;
                ldsm_x2(bfr[j], Bs_u + (uint32_t)(cb * STR_H + k0) * 2u + b_off);
            }
#pragma unroll
            for (int i = 0; i < 4; i++)
#pragma unroll
                for (int j = 0; j < 4; j++)
                    mma_fp16(acc[i][j], afr[i], bfr[j]);
        }
    }

#pragma unroll
    for (int i = 0; i < 4; i++) {
#pragma unroll
        for (int j = 0; j < 4; j++) {
            int col = n0 + wn * 32 + j * 8 + tig * 2;
#pragma unroll
            for (int half_ = 0; half_ < 2; half_++) {
                int row = m0 + wm * 64 + i * 16 + gid + half_ * 8;
                float vx = acc[i][j][half_ * 2 + 0];
                float vy = acc[i][j][half_ * 2 + 1];
                if (EPI == 0) {
                    __half* Ch = (__half*)Cp;
                    *(__half2*)&Ch[(size_t)row * N + col] = __floats2half2_rn(vx, vy);
                } else if (EPI == 1) {
                    const float* rrow = res + (size_t)row * N + col;
                    vx += bias[col]     + rrow[0];
                    vy += bias[col + 1] + rrow[1];
                    *(float2*)((float*)Cp + (size_t)row * N + col) = make_float2(vx, vy);
                } else {
                    vx += bias[col];
                    vy += bias[col + 1];
                    vx = 0.5f * vx * (1.0f + erff(vx * 0.70710678118654752f));
                    vy = 0.5f * vy * (1.0f + erff(vy * 0.70710678118654752f));
                    __half* Ch = (__half*)Cp;
                    *(__half2*)&Ch[(size_t)row * N + col] = __floats2half2_rn(vx, vy);
                }
            }
        }
    }
}

template<int EPI>
__global__ __launch_bounds__(256, 1) void tc_gemm(
    const __half* __restrict__ A, const __half* __restrict__ B,
    const float* __restrict__ bias, const float* __restrict__ res,
    void* __restrict__ C, int M, int N, int K)
{
    gemm_body<EPI>(A, B, bias, res, C, M, N, K, blockIdx.x, blockIdx.y);
}

__global__ __launch_bounds__(256, 1) void qkv_gemm(
    const __half* __restrict__ A,
    const __half* __restrict__ Wq, const __half* __restrict__ Wk, const __half* __restrict__ Wv,
    __half* __restrict__ Oq, __half* __restrict__ Ok, __half* __restrict__ Ov)
{
    const __half* B;
    __half* C;
    int z = blockIdx.z;
    if (z == 0)      { B = Wq; C = Oq; }
    else if (z == 1) { B = Wk; C = Ok; }
    else             { B = Wv; C = Ov; }
    gemm_body<0>(A, B, nullptr, nullptr, (void*)C, MROWS, 2*CC, CC, blockIdx.x, blockIdx.y);
}

// ================= Fused differential flash attention ========================
// grid (8, 12, 4): x=q-tile(128 rows), y=head, z=batch. 8 warps x 16 rows.
// Sequential splits; split-0 normalized output parked in f32 smem; epilogue
// does diff + per-row LN(128) + *0.8 and stores half att directly.
#define SQS 72
#define SKS 72
#define SVS 136
#define SQ_H (128*SQS)
#define SK_H (64*SKS)
#define SV_H (64*SVS)
#define SO_STR 132
#define SO_F (128*SO_STR)
#define ATT_SMEM ((SQ_H+SK_H+SV_H)*2 + SO_F*4)   // 45056 + 67584 = 112640

__global__ __launch_bounds__(256, 2) void attn_mma_kernel(
    const __half* __restrict__ Q, const __half* __restrict__ K,
    const __half* __restrict__ Vv, const float* __restrict__ lamp,
    const float* __restrict__ lnw, const float* __restrict__ lnb,
    __half* __restrict__ att)
{
    extern __shared__ __half ash[];
    __half* sQh = ash;
    __half* sKh = ash + SQ_H;
    __half* sVh = ash + SQ_H + SK_H;
    float*  sO  = (float*)(ash + SQ_H + SK_H + SV_H);
    uint32_t sv_base = smem_u32(sVh);

    int tid  = threadIdx.x;
    int wid  = tid >> 5;
    int lane = tid & 31;
    int gid  = lane >> 2;
    int tig  = lane & 3;

    int q0 = blockIdx.x * 128;
    int h  = blockIdx.y;
    int b  = blockIdx.z;
    size_t base = (size_t)b * NN;
    int vcol = h * TWO_D;
    float lam = lamp[0];

    int rl0 = wid * 16 + gid;       // local rows 0..127
    int rl1 = rl0 + 8;

    float o[16][4];

    for (int sp = 0; sp < 2; sp++) {
        int qkcol = h * TWO_D + sp * 64;
        __syncthreads();   // protect sQ/sK/sV from previous split's reads

        // stage Q (x SCALE, exact power of two)
        {
            int seg = tid & 7, r0 = tid >> 3;
            __half2 smul = __float2half2_rn(SCALE);
#pragma unroll
            for (int p = 0; p < 4; p++) {
                int r = r0 + p * 32;
                float4 qv = *(const float4*)&Q[(base + q0 + r) * (2*CC) + qkcol + seg * 8];
                __half2* qh = (__half2*)&qv;
                qh[0] = __hmul2(qh[0], smul); qh[1] = __hmul2(qh[1], smul);
                qh[2] = __hmul2(qh[2], smul); qh[3] = __hmul2(qh[3], smul);
                *(float4*)&sQh[r * SQS + seg * 8] = qv;
            }
        }

#pragma unroll
        for (int j = 0; j < 16; j++)
#pragma unroll
            for (int r = 0; r < 4; r++) o[j][r] = 0.f;
        float m0 = -1e30f, m1 = -1e30f, l0 = 0.f, l1 = 0.f;

        for (int t = 0; t < NN / 64; t++) {
            __syncthreads();
            {
                int seg = tid & 7, r0 = tid >> 3;
#pragma unroll
                for (int p = 0; p < 2; p++) {
                    int r = r0 + p * 32;
                    float4 kv = *(const float4*)&K[(base + t*64 + r) * (2*CC) + qkcol + seg * 8];
                    *(float4*)&sKh[r * SKS + seg * 8] = kv;
                }
                int seg16 = tid & 15, r0v = tid >> 4;
#pragma unroll
                for (int p = 0; p < 4; p++) {
                    int r = r0v + p * 16;
                    float4 vv = *(const float4*)&Vv[(base + t*64 + r) * (2*CC) + vcol + seg16 * 8];
                    *(float4*)&sVh[r * SVS + seg16 * 8] = vv;
                }
            }
            __syncthreads();

            // S = Q K^T
            float s_[8][4];
#pragma unroll
            for (int j = 0; j < 8; j++)
#pragma unroll
                for (int r = 0; r < 4; r++) s_[j][r] = 0.f;
            int ar = wid * 16 + gid;
#pragma unroll
            for (int ks = 0; ks < 4; ks++) {
                int k0 = ks * 16;
                uint32_t a[4];
                a[0] = *(const uint32_t*)&sQh[ ar      * SQS + k0 + tig*2];
                a[1] = *(const uint32_t*)&sQh[(ar + 8) * SQS + k0 + tig*2];
                a[2] = *(const uint32_t*)&sQh[ ar      * SQS + k0 + 8 + tig*2];
                a[3] = *(const uint32_t*)&sQh[(ar + 8) * SQS + k0 + 8 + tig*2];
#pragma unroll
                for (int j = 0; j < 8; j++) {
                    uint32_t bfr[2];
                    bfr[0] = *(const uint32_t*)&sKh[(j*8 + gid) * SKS + k0 + tig*2];
                    bfr[1] = *(const uint32_t*)&sKh[(j*8 + gid) * SKS + k0 + 8 + tig*2];
                    mma_fp16(s_[j], a, bfr);
                }
            }

            // online softmax
            float rm0 = -1e30f, rm1 = -1e30f;
#pragma unroll
            for (int j = 0; j < 8; j++) {
                rm0 = fmaxf(rm0, fmaxf(s_[j][0], s_[j][1]));
                rm1 = fmaxf(rm1, fmaxf(s_[j][2], s_[j][3]));
            }
            rm0 = fmaxf(rm0, __shfl_xor_sync(0xffffffffu, rm0, 1));
            rm0 = fmaxf(rm0, __shfl_xor_sync(0xffffffffu, rm0, 2));
            rm1 = fmaxf(rm1, __shfl_xor_sync(0xffffffffu, rm1, 1));
            rm1 = fmaxf(rm1, __shfl_xor_sync(0xffffffffu, rm1, 2));
            float nm0 = fmaxf(m0, rm0), nm1 = fmaxf(m1, rm1);
            float f0 = __expf(m0 - nm0), f1 = __expf(m1 - nm1);
            float rs0 = 0.f, rs1 = 0.f;
#pragma unroll
            for (int j = 0; j < 8; j++) {
                s_[j][0] = __expf(s_[j][0] - nm0);
                s_[j][1] = __expf(s_[j][1] - nm0);
                s_[j][2] = __expf(s_[j][2] - nm1);
                s_[j][3] = __expf(s_[j][3] - nm1);
                rs0 += s_[j][0] + s_[j][1];
                rs1 += s_[j][2] + s_[j][3];
            }
            rs0 += __shfl_xor_sync(0xffffffffu, rs0, 1);
            rs0 += __shfl_xor_sync(0xffffffffu, rs0, 2);
            rs1 += __shfl_xor_sync(0xffffffffu, rs1, 1);
            rs1 += __shfl_xor_sync(0xffffffffu, rs1, 2);
            l0 = l0 * f0 + rs0;
            l1 = l1 * f1 + rs1;
            m0 = nm0; m1 = nm1;
#pragma unroll
            for (int j = 0; j < 16; j++) {
                o[j][0] *= f0; o[j][1] *= f0;
                o[j][2] *= f1; o[j][3] *= f1;
            }

            // O += P @ V (P C-fragment == A-fragment; V via ldmatrix trans)
#pragma unroll
            for (int kc = 0; kc < 4; kc++) {
                uint32_t a[4];
                a[0] = f22h2(s_[2*kc  ][0], s_[2*kc  ][1]);
                a[1] = f22h2(s_[2*kc  ][2], s_[2*kc  ][3]);
                a[2] = f22h2(s_[2*kc+1][0], s_[2*kc+1][1]);
                a[3] = f22h2(s_[2*kc+1][2], s_[2*kc+1][3]);
                uint32_t rowaddr = sv_base + (uint32_t)((kc*16 + (lane & 15)) * SVS) * 2u;
#pragma unroll
                for (int j = 0; j < 16; j++) {
                    uint32_t b0, b1;
                    ldsm_x2_trans(b0, b1, rowaddr + j * 16);
                    uint32_t bfr[2] = {b0, b1};
                    mma_fp16(o[j], a, bfr);
                }
            }
        }

        float inv0 = 1.f / l0, inv1 = 1.f / l1;
        if (sp == 0) {
            // park normalized split-0 output in f32 smem (thread-private slots)
#pragma unroll
            for (int j = 0; j < 16; j++) {
                int col = j*8 + tig*2;
                *(float2*)&sO[rl0 * SO_STR + col] = make_float2(o[j][0]*inv0, o[j][1]*inv0);
                *(float2*)&sO[rl1 * SO_STR + col] = make_float2(o[j][2]*inv1, o[j][3]*inv1);
            }
        } else {
            // combine: v = o1 - lam*o2, then per-row LN over 128 dims
            float sum0 = 0.f, sum1 = 0.f, sq0 = 0.f, sq1 = 0.f;
#pragma unroll
            for (int j = 0; j < 16; j++) {
                int col = j*8 + tig*2;
                float2 p0 = *(float2*)&sO[rl0 * SO_STR + col];
                float2 p1 = *(float2*)&sO[rl1 * SO_STR + col];
                float v0x = p0.x - lam * (o[j][0]*inv0);
                float v0y = p0.y - lam * (o[j][1]*inv0);
                float v1x = p1.x - lam * (o[j][2]*inv1);
                float v1y = p1.y - lam * (o[j][3]*inv1);
                o[j][0] = v0x; o[j][1] = v0y; o[j][2] = v1x; o[j][3] = v1y;
                sum0 += v0x + v0y;  sq0 += v0x*v0x + v0y*v0y;
                sum1 += v1x + v1y;  sq1 += v1x*v1x + v1y*v1y;
            }
            sum0 += __shfl_xor_sync(0xffffffffu, sum0, 1);
            sum0 += __shfl_xor_sync(0xffffffffu, sum0, 2);
            sq0  += __shfl_xor_sync(0xffffffffu, sq0, 1);
            sq0  += __shfl_xor_sync(0xffffffffu, sq0, 2);
            sum1 += __shfl_xor_sync(0xffffffffu, sum1, 1);
            sum1 += __shfl_xor_sync(0xffffffffu, sum1, 2);
            sq1  += __shfl_xor_sync(0xffffffffu, sq1, 1);
            sq1  += __shfl_xor_sync(0xffffffffu, sq1, 2);
            float mu0 = sum0 * (1.0f/128.0f);
            float mu1 = sum1 * (1.0f/128.0f);
            float rstd0 = rsqrtf(sq0 * (1.0f/128.0f) - mu0*mu0 + EPS);
            float rstd1 = rsqrtf(sq1 * (1.0f/128.0f) - mu1*mu1 + EPS);
            size_t grow0 = base + q0 + rl0;
            size_t grow1 = base + q0 + rl1;
#pragma unroll
            for (int j = 0; j < 16; j++) {
                int col = j*8 + tig*2;
                float lw0 = lnw[col], lw1 = lnw[col+1];
                float lb0 = lnb[col], lb1 = lnb[col+1];
                float y0x = ((o[j][0] - mu0) * rstd0 * lw0 + lb0) * OUT_SCALE;
                float y0y = ((o[j][1] - mu0) * rstd0 * lw1 + lb1) * OUT_SCALE;
                float y1x = ((o[j][2] - mu1) * rstd1 * lw0 + lb0) * OUT_SCALE;
                float y1y = ((o[j][3] - mu1) * rstd1 * lw1 + lb1) * OUT_SCALE;
                *(__half2*)&att[grow0 * (2*CC) + vcol + col] = __floats2half2_rn(y0x, y0y);
                *(__half2*)&att[grow1 * (2*CC) + vcol + col] = __floats2half2_rn(y1x, y1y);
            }
        }
    }
}

// ================= launch =================
extern "C" void kernel_launch(void* const* d_in, const int* in_sizes, int n_in,
                              void* d_out, int out_size)
{
    const float* x    = (const float*)d_in[0];
    const float* n1w  = (const float*)d_in[1];
    const float* n1b  = (const float*)d_in[2];
    const float* wq   = (const float*)d_in[3];
    const float* wk   = (const float*)d_in[4];
    const float* wv   = (const float*)d_in[5];
    const float* lam  = (const float*)d_in[6];
    const float* alnw = (const float*)d_in[7];
    const float* alnb = (const float*)d_in[8];
    const float* pw   = (const float*)d_in[9];
    const float* pb   = (const float*)d_in[10];
    const float* n2w  = (const float*)d_in[11];
    const float* n2b  = (const float*)d_in[12];
    const float* f1w  = (const float*)d_in[13];
    const float* f1b  = (const float*)d_in[14];
    const float* f2w  = (const float*)d_in[15];
    const float* f2b  = (const float*)d_in[16];
    float* out = (float*)d_out;

    __half *xn, *q, *k, *v, *att, *xn2, *hb;
    float *xmid;
    __half *cwq, *cwk, *cwv, *cpw, *cf1, *cf2;
    cudaGetSymbolAddress((void**)&xn,   g_xn);
    cudaGetSymbolAddress((void**)&q,    g_q);
    cudaGetSymbolAddress((void**)&k,    g_k);
    cudaGetSymbolAddress((void**)&v,    g_v);
    cudaGetSymbolAddress((void**)&att,  g_att);
    cudaGetSymbolAddress((void**)&xmid, g_xmid);
    cudaGetSymbolAddress((void**)&xn2,  g_xn2);
    cudaGetSymbolAddress((void**)&hb,   g_h);
    cudaGetSymbolAddress((void**)&cwq,  g_wq);
    cudaGetSymbolAddress((void**)&cwk,  g_wk);
    cudaGetSymbolAddress((void**)&cwv,  g_wv);
    cudaGetSymbolAddress((void**)&cpw,  g_pw);
    cudaGetSymbolAddress((void**)&cf1,  g_f1);
    cudaGetSymbolAddress((void**)&cf2,  g_f2);

    cudaFuncSetAttribute(attn_mma_kernel,
                         cudaFuncAttributeMaxDynamicSharedMemorySize, ATT_SMEM);
    cudaFuncSetAttribute(qkv_gemm,
                         cudaFuncAttributeMaxDynamicSharedMemorySize, GEMM_SMEM_BYTES);
    cudaFuncSetAttribute(tc_gemm<1>,
                         cudaFuncAttributeMaxDynamicSharedMemorySize, GEMM_SMEM_BYTES);
    cudaFuncSetAttribute(tc_gemm<2>,
                         cudaFuncAttributeMaxDynamicSharedMemorySize, GEMM_SMEM_BYTES);

    // 0. weight fp16 pre-conversion
    {
        int n4a = (2*CC*CC)/4;
        int n4b = (4*CC*CC)/4;
        cvtw_kernel<<<(n4a+255)/256, 256>>>(wq,  cwq, n4a);
        cvtw_kernel<<<(n4a+255)/256, 256>>>(wk,  cwk, n4a);
        cvtw_kernel<<<(n4a+255)/256, 256>>>(wv,  cwv, n4a);
        cvtw_kernel<<<(n4a+255)/256, 256>>>(pw,  cpw, n4a);
        cvtw_kernel<<<(n4b+255)/256, 256>>>(f1w, cf1, n4b);
        cvtw_kernel<<<(n4b+255)/256, 256>>>(f2w, cf2, n4b);
    }
    // 1. LN1 (fp16 output)
    ln_kernel<<<MROWS, 256>>>(x, n1w, n1b, xn);
    // 2. merged QKV GEMM (fp16), one launch
    qkv_gemm<<<dim3(1536/128, MROWS/128, 3), 256, GEMM_SMEM_BYTES>>>(xn, cwq, cwk, cwv, q, k, v);
    // 3. fused differential flash attention + combine + head-LN (half att out)
    attn_mma_kernel<<<dim3(NN/128, HH, BB), 256, ATT_SMEM>>>(q, k, v, lam, alnw, alnb, att);
    // 4. proj + bias + residual (f32 out)
    tc_gemm<1><<<dim3(768/128, MROWS/128), 256, GEMM_SMEM_BYTES>>>(att, cpw, pb, x, xmid, MROWS, 768, 1536);
    // 5. LN2 (fp16 output)
    ln_kernel<<<MROWS, 256>>>(xmid, n2w, n2b, xn2);
    // 6. fc1 + bias + GELU (fp16 out)
    tc_gemm<2><<<dim3(3072/128, MROWS/128), 256, GEMM_SMEM_BYTES>>>(xn2, cf1, f1b, nullptr, hb, MROWS, 3072, 768);
    // 7. fc2 + bias + residual (f32 out)
    tc_gemm<1><<<dim3(768/128, MROWS/128), 256, GEMM_SMEM_BYTES>>>(hb, cf2, f2b, xmid, out, MROWS, 768, 3072);
}

// round 12
// speedup vs baseline: 2.0990x; 1.0473x over previous
#include <cuda_runtime.h>
#include <cuda_fp16.h>
#include <math.h>
#include <stdint.h>

// ---------------- problem constants ----------------
#define BB 4
#define NN 1024
#define CC 768
#define HH 12
#define TWO_D 128
#define MROWS (BB*NN)    // 4096
#define SCALE 0.125f     // D^-0.5
#define EPS 1e-5f
#define OUT_SCALE 0.8f   // 1 - LAMBDA_INIT

// ---------------- scratch (device globals; no alloc allowed) ----------------
__device__ __half g_xn  [MROWS*CC];
__device__ __half g_q   [MROWS*2*CC];
__device__ __half g_k   [MROWS*2*CC];
__device__ __half g_v   [MROWS*2*CC];
__device__ __half g_att [MROWS*2*CC];
__device__ float  g_xmid[MROWS*CC];
__device__ __half g_xn2 [MROWS*CC];
__device__ __half g_h   [MROWS*4*CC];
// converted fp16 weights
__device__ __half g_wq [2*CC*CC];
__device__ __half g_wk [2*CC*CC];
__device__ __half g_wv [2*CC*CC];
__device__ __half g_pw [CC*2*CC];
__device__ __half g_f1 [4*CC*CC];
__device__ __half g_f2 [CC*4*CC];

// ================= helpers =================
__device__ __forceinline__ uint32_t f22h2(float a, float b) {
    __half2 h = __floats2half2_rn(a, b);
    return *reinterpret_cast<uint32_t*>(&h);
}
__device__ __forceinline__ void mma_fp16(float* c, const uint32_t* a, const uint32_t* b) {
    asm volatile("mma.sync.aligned.m16n8k16.row.col.f32.f16.f16.f32 "
        "{%0,%1,%2,%3}, {%4,%5,%6,%7}, {%8,%9}, {%0,%1,%2,%3};"
        : "+f"(c[0]), "+f"(c[1]), "+f"(c[2]), "+f"(c[3])
        : "r"(a[0]), "r"(a[1]), "r"(a[2]), "r"(a[3]), "r"(b[0]), "r"(b[1]));
}
__device__ __forceinline__ void ldsm_x4(uint32_t* r, uint32_t addr) {
    asm volatile("ldmatrix.sync.aligned.m8n8.x4.shared.b16 {%0,%1,%2,%3}, [%4];"
        : "=r"(r[0]), "=r"(r[1]), "=r"(r[2]), "=r"(r[3]) : "r"(addr));
}
__device__ __forceinline__ void ldsm_x2(uint32_t* r, uint32_t addr) {
    asm volatile("ldmatrix.sync.aligned.m8n8.x2.shared.b16 {%0,%1}, [%2];"
        : "=r"(r[0]), "=r"(r[1]) : "r"(addr));
}
__device__ __forceinline__ void ldsm_x2_trans(uint32_t& r0, uint32_t& r1, uint32_t addr) {
    asm volatile("ldmatrix.sync.aligned.m8n8.x2.trans.shared.b16 {%0,%1}, [%2];"
        : "=r"(r0), "=r"(r1) : "r"(addr));
}
__device__ __forceinline__ uint32_t smem_u32(const void* p) {
    uint32_t a;
    asm("{ .reg .u64 t; cvta.to.shared.u64 t, %1; cvt.u32.u64 %0, t; }" : "=r"(a) : "l"(p));
    return a;
}
__device__ __forceinline__ void cp16(uint32_t dst, const void* src) {
    asm volatile("cp.async.ca.shared.global [%0], [%1], 16;" :: "r"(dst), "l"(src));
}
__device__ __forceinline__ void cp_commit() {
    asm volatile("cp.async.commit_group;" ::: "memory");
}
__device__ __forceinline__ void cp_wait1() {
    asm volatile("cp.async.wait_group 1;" ::: "memory");
}

// ================= merged weight fp16 pre-conversion =========================
// grid (2304, 6): y selects tensor; oversized x early-exits.
__global__ __launch_bounds__(256) void cvtw_all_kernel(
    const float* __restrict__ s0, __half* __restrict__ d0, int n0,
    const float* __restrict__ s1, __half* __restrict__ d1, int n1,
    const float* __restrict__ s2, __half* __restrict__ d2, int n2,
    const float* __restrict__ s3, __half* __restrict__ d3, int n3,
    const float* __restrict__ s4, __half* __restrict__ d4, int n4,
    const float* __restrict__ s5, __half* __restrict__ d5, int n5)
{
    const float* s; __half* d; int n;
    switch (blockIdx.y) {
        case 0: s = s0; d = d0; n = n0; break;
        case 1: s = s1; d = d1; n = n1; break;
        case 2: s = s2; d = d2; n = n2; break;
        case 3: s = s3; d = d3; n = n3; break;
        case 4: s = s4; d = d4; n = n4; break;
        default: s = s5; d = d5; n = n5; break;
    }
    int i = blockIdx.x * 256 + threadIdx.x;
    if (i < n) {
        float4 v = ((const float4*)s)[i];
        __half2* dp = (__half2*)d;
        dp[i*2 + 0] = __floats2half2_rn(v.x, v.y);
        dp[i*2 + 1] = __floats2half2_rn(v.z, v.w);
    }
}

// ================= LayerNorm over 768 (fp16 output) =================
__global__ __launch_bounds__(256) void ln_kernel(
    const float* __restrict__ x, const float* __restrict__ w,
    const float* __restrict__ b, __half* __restrict__ out)
{
    int row = blockIdx.x;
    int tid = threadIdx.x;
    const float* xr = x + (size_t)row * CC;
    float v0 = xr[tid], v1 = xr[tid + 256], v2 = xr[tid + 512];
    float s  = v0 + v1 + v2;
    float sq = v0*v0 + v1*v1 + v2*v2;
#pragma unroll
    for (int off = 16; off >= 1; off >>= 1) {
        s  += __shfl_xor_sync(0xffffffffu, s,  off);
        sq += __shfl_xor_sync(0xffffffffu, sq, off);
    }
    __shared__ float rs_[8], rq_[8];
    __shared__ float smu, srs;
    int wid = tid >> 5, lane = tid & 31;
    if (lane == 0) { rs_[wid] = s; rq_[wid] = sq; }
    __syncthreads();
    if (tid == 0) {
        float S = 0.f, Q = 0.f;
#pragma unroll
        for (int i = 0; i < 8; i++) { S += rs_[i]; Q += rq_[i]; }
        float mu = S / (float)CC;
        float var = Q / (float)CC - mu * mu;
        smu = mu; srs = rsqrtf(var + EPS);
    }
    __syncthreads();
    float mu = smu, r = srs;
    __half* orow = out + (size_t)row * CC;
    orow[tid]       = __float2half_rn((v0 - mu) * r * w[tid]       + b[tid]);
    orow[tid + 256] = __float2half_rn((v1 - mu) * r * w[tid + 256] + b[tid + 256]);
    orow[tid + 512] = __float2half_rn((v2 - mu) * r * w[tid + 512] + b[tid + 512]);
}

// ================= FP16 mma.sync GEMM, cp.async pipeline + ldmatrix ==========
// Tile: TM x 128 (TM = 128 or 64). 8 warps (2m x 4n); warp tile (TM/2) x 32.
#define KC 64
#define STR_H 72
#define GSTAGES 3
#define STAGE_B_BYTES (128 * STR_H * 2)
#define STAGE_A_BYTES(TM) ((TM) * STR_H * 2)
#define GEMM_SMEM(TM) (GSTAGES * (STAGE_A_BYTES(TM) + STAGE_B_BYTES))

template<int EPI, int TM>
__device__ __forceinline__ void gemm_body(
    const __half* __restrict__ A, const __half* __restrict__ B,
    const float* __restrict__ bias, const float* __restrict__ res,
    void* __restrict__ Cp, int M, int N, int K, int bx, int by)
{
    constexpr int IFR = TM / 32;                  // i-fragments per warp
    constexpr int STAGE_BYTES_ = STAGE_A_BYTES(TM) + STAGE_B_BYTES;

    extern __shared__ __half gsmh[];
    uint32_t sb = smem_u32(gsmh);

    int tid  = threadIdx.x;
    int wid  = tid >> 5;
    int lane = tid & 31;
    int wm = wid >> 2;
    int wn = wid & 3;
    int gid = lane >> 2;
    int tig = lane & 3;

    int m0 = by * TM, n0 = bx * 128;
    int seg = tid & 7;
    int r0  = tid >> 3;

    uint32_t a_off = (uint32_t)((lane & 15) * STR_H + (lane >> 4) * 8) * 2u;
    uint32_t b_off = (uint32_t)((lane & 7) * STR_H + ((lane >> 3) & 1) * 8) * 2u;

    float acc[IFR][4][4];
#pragma unroll
    for (int i = 0; i < IFR; i++)
#pragma unroll
        for (int j = 0; j < 4; j++)
#pragma unroll
            for (int r = 0; r < 4; r++) acc[i][j][r] = 0.f;

    int Cn = K / KC;

    auto issue = [&](int c) {
        int s = c % GSTAGES;
        uint32_t abase = sb + (uint32_t)s * STAGE_BYTES_;
        uint32_t bbase = abase + STAGE_A_BYTES(TM);
        int k0 = c * KC;
#pragma unroll
        for (int p = 0; p < TM/32; p++) {
            int r = r0 + p * 32;
            uint32_t soff = (uint32_t)(r * STR_H + seg * 8) * 2u;
            cp16(abase + soff, A + (size_t)(m0 + r) * K + k0 + seg * 8);
        }
#pragma unroll
        for (int p = 0; p < 4; p++) {
            int r = r0 + p * 32;
            uint32_t soff = (uint32_t)(r * STR_H + seg * 8) * 2u;
            cp16(bbase + soff, B + (size_t)(n0 + r) * K + k0 + seg * 8);
        }
    };

    issue(0); cp_commit();
    issue(1); cp_commit();

    for (int c = 0; c < Cn; c++) {
        cp_wait1();
        __syncthreads();
        if (c + 2 < Cn) issue(c + 2);
        cp_commit();

        uint32_t As_u = sb + (uint32_t)(c % GSTAGES) * STAGE_BYTES_;
        uint32_t Bs_u = As_u + STAGE_A_BYTES(TM);
#pragma unroll
        for (int ks = 0; ks < 4; ks++) {
            int k0 = ks * 16;
            uint32_t afr[IFR][4], bfr[4][2];
#pragma unroll
            for (int i = 0; i < IFR; i++) {
                int rb = wm * (TM/2) + i * 16;
                ldsm_x4(afr[i], As_u + (uint32_t)(rb * STR_H + k0) * 2u + a_off);
            }
#pragma unroll
            for (int j = 0; j < 4; j++) {
                int cb = wn * 32 + j * 8;
                ldsm_x2(bfr[j], Bs_u + (uint32_t)(cb * STR_H + k0) * 2u + b_off);
            }
#pragma unroll
            for (int i = 0; i < IFR; i++)
#pragma unroll
                for (int j = 0; j < 4; j++)
                    mma_fp16(acc[i][j], afr[i], bfr[j]);
        }
    }

#pragma unroll
    for (int i = 0; i < IFR; i++) {
#pragma unroll
        for (int j = 0; j < 4; j++) {
            int col = n0 + wn * 32 + j * 8 + tig * 2;
#pragma unroll
            for (int half_ = 0; half_ < 2; half_++) {
                int row = m0 + wm * (TM/2) + i * 16 + gid + half_ * 8;
                float vx = acc[i][j][half_ * 2 + 0];
                float vy = acc[i][j][half_ * 2 + 1];
                if (EPI == 0) {
                    __half* Ch = (__half*)Cp;
                    *(__half2*)&Ch[(size_t)row * N + col] = __floats2half2_rn(vx, vy);
                } else if (EPI == 1) {
                    const float* rrow = res + (size_t)row * N + col;
                    vx += bias[col]     + rrow[0];
                    vy += bias[col + 1] + rrow[1];
                    *(float2*)((float*)Cp + (size_t)row * N + col) = make_float2(vx, vy);
                } else {
                    vx += bias[col];
                    vy += bias[col + 1];
                    vx = 0.5f * vx * (1.0f + erff(vx * 0.70710678118654752f));
                    vy = 0.5f * vy * (1.0f + erff(vy * 0.70710678118654752f));
                    __half* Ch = (__half*)Cp;
                    *(__half2*)&Ch[(size_t)row * N + col] = __floats2half2_rn(vx, vy);
                }
            }
        }
    }
}

template<int EPI, int TM>
__global__ __launch_bounds__(256, 1) void tc_gemm(
    const __half* __restrict__ A, const __half* __restrict__ B,
    const float* __restrict__ bias, const float* __restrict__ res,
    void* __restrict__ C, int M, int N, int K)
{
    gemm_body<EPI, TM>(A, B, bias, res, C, M, N, K, blockIdx.x, blockIdx.y);
}

__global__ __launch_bounds__(256, 1) void qkv_gemm(
    const __half* __restrict__ A,
    const __half* __restrict__ Wq, const __half* __restrict__ Wk, const __half* __restrict__ Wv,
    __half* __restrict__ Oq, __half* __restrict__ Ok, __half* __restrict__ Ov)
{
    const __half* B;
    __half* C;
    int z = blockIdx.z;
    if (z == 0)      { B = Wq; C = Oq; }
    else if (z == 1) { B = Wk; C = Ok; }
    else             { B = Wv; C = Ov; }
    gemm_body<0, 128>(A, B, nullptr, nullptr, (void*)C, MROWS, 2*CC, CC, blockIdx.x, blockIdx.y);
}

// ================= Fused differential flash attention ========================
#define SQS 72
#define SKS 72
#define SVS 136
#define SQ_H (128*SQS)
#define SK_H (64*SKS)
#define SV_H (64*SVS)
#define SO_STR 132
#define SO_F (128*SO_STR)
#define ATT_SMEM ((SQ_H+SK_H+SV_H)*2 + SO_F*4)   // 112640

__global__ __launch_bounds__(256, 2) void attn_mma_kernel(
    const __half* __restrict__ Q, const __half* __restrict__ K,
    const __half* __restrict__ Vv, const float* __restrict__ lamp,
    const float* __restrict__ lnw, const float* __restrict__ lnb,
    __half* __restrict__ att)
{
    extern __shared__ __half ash[];
    __half* sQh = ash;
    __half* sKh = ash + SQ_H;
    __half* sVh = ash + SQ_H + SK_H;
    float*  sO  = (float*)(ash + SQ_H + SK_H + SV_H);
    uint32_t sv_base = smem_u32(sVh);

    int tid  = threadIdx.x;
    int wid  = tid >> 5;
    int lane = tid & 31;
    int gid  = lane >> 2;
    int tig  = lane & 3;

    int q0 = blockIdx.x * 128;
    int h  = blockIdx.y;
    int b  = blockIdx.z;
    size_t base = (size_t)b * NN;
    int vcol = h * TWO_D;
    float lam = lamp[0];

    int rl0 = wid * 16 + gid;
    int rl1 = rl0 + 8;

    float o[16][4];

    for (int sp = 0; sp < 2; sp++) {
        int qkcol = h * TWO_D + sp * 64;
        __syncthreads();

        {
            int seg = tid & 7, r0 = tid >> 3;
            __half2 smul = __float2half2_rn(SCALE);
#pragma unroll
            for (int p = 0; p < 4; p++) {
                int r = r0 + p * 32;
                float4 qv = *(const float4*)&Q[(base + q0 + r) * (2*CC) + qkcol + seg * 8];
                __half2* qh = (__half2*)&qv;
                qh[0] = __hmul2(qh[0], smul); qh[1] = __hmul2(qh[1], smul);
                qh[2] = __hmul2(qh[2], smul); qh[3] = __hmul2(qh[3], smul);
                *(float4*)&sQh[r * SQS + seg * 8] = qv;
            }
        }

#pragma unroll
        for (int j = 0; j < 16; j++)
#pragma unroll
            for (int r = 0; r < 4; r++) o[j][r] = 0.f;
        float m0 = -1e30f, m1 = -1e30f, l0 = 0.f, l1 = 0.f;

        for (int t = 0; t < NN / 64; t++) {
            __syncthreads();
            {
                int seg = tid & 7, r0 = tid >> 3;
#pragma unroll
                for (int p = 0; p < 2; p++) {
                    int r = r0 + p * 32;
                    float4 kv = *(const float4*)&K[(base + t*64 + r) * (2*CC) + qkcol + seg * 8];
                    *(float4*)&sKh[r * SKS + seg * 8] = kv;
                }
                int seg16 = tid & 15, r0v = tid >> 4;
#pragma unroll
                for (int p = 0; p < 4; p++) {
                    int r = r0v + p * 16;
                    float4 vv = *(const float4*)&Vv[(base + t*64 + r) * (2*CC) + vcol + seg16 * 8];
                    *(float4*)&sVh[r * SVS + seg16 * 8] = vv;
                }
            }
            __syncthreads();

            float s_[8][4];
#pragma unroll
            for (int j = 0; j < 8; j++)
#pragma unroll
                for (int r = 0; r < 4; r++) s_[j][r] = 0.f;
            int ar = wid * 16 + gid;
#pragma unroll
            for (int ks = 0; ks < 4; ks++) {
                int k0 = ks * 16;
                uint32_t a[4];
                a[0] = *(const uint32_t*)&sQh[ ar      * SQS + k0 + tig*2];
                a[1] = *(const uint32_t*)&sQh[(ar + 8) * SQS + k0 + tig*2];
                a[2] = *(const uint32_t*)&sQh[ ar      * SQS + k0 + 8 + tig*2];
                a[3] = *(const uint32_t*)&sQh[(ar + 8) * SQS + k0 + 8 + tig*2];
#pragma unroll
                for (int j = 0; j < 8; j++) {
                    uint32_t bfr[2];
                    bfr[0] = *(const uint32_t*)&sKh[(j*8 + gid) * SKS + k0 + tig*2];
                    bfr[1] = *(const uint32_t*)&sKh[(j*8 + gid) * SKS + k0 + 8 + tig*2];
                    mma_fp16(s_[j], a, bfr);
                }
            }

            float rm0 = -1e30f, rm1 = -1e30f;
#pragma unroll
            for (int j = 0; j < 8; j++) {
                rm0 = fmaxf(rm0, fmaxf(s_[j][0], s_[j][1]));
                rm1 = fmaxf(rm1, fmaxf(s_[j][2], s_[j][3]));
            }
            rm0 = fmaxf(rm0, __shfl_xor_sync(0xffffffffu, rm0, 1));
            rm0 = fmaxf(rm0, __shfl_xor_sync(0xffffffffu, rm0, 2));
            rm1 = fmaxf(rm1, __shfl_xor_sync(0xffffffffu, rm1, 1));
            rm1 = fmaxf(rm1, __shfl_xor_sync(0xffffffffu, rm1, 2));
            float nm0 = fmaxf(m0, rm0), nm1 = fmaxf(m1, rm1);
            float f0 = __expf(m0 - nm0), f1 = __expf(m1 - nm1);
            float rs0 = 0.f, rs1 = 0.f;
#pragma unroll
            for (int j = 0; j < 8; j++) {
                s_[j][0] = __expf(s_[j][0] - nm0);
                s_[j][1] = __expf(s_[j][1] - nm0);
                s_[j][2] = __expf(s_[j][2] - nm1);
                s_[j][3] = __expf(s_[j][3] - nm1);
                rs0 += s_[j][0] + s_[j][1];
                rs1 += s_[j][2] + s_[j][3];
            }
            rs0 += __shfl_xor_sync(0xffffffffu, rs0, 1);
            rs0 += __shfl_xor_sync(0xffffffffu, rs0, 2);
            rs1 += __shfl_xor_sync(0xffffffffu, rs1, 1);
            rs1 += __shfl_xor_sync(0xffffffffu, rs1, 2);
            l0 = l0 * f0 + rs0;
            l1 = l1 * f1 + rs1;
            m0 = nm0; m1 = nm1;
#pragma unroll
            for (int j = 0; j < 16; j++) {
                o[j][0] *= f0; o[j][1] *= f0;
                o[j][2] *= f1; o[j][3] *= f1;
            }

#pragma unroll
            for (int kc = 0; kc < 4; kc++) {
                uint32_t a[4];
                a[0] = f22h2(s_[2*kc  ][0], s_[2*kc  ][1]);
                a[1] = f22h2(s_[2*kc  ][2], s_[2*kc  ][3]);
                a[2] = f22h2(s_[2*kc+1][0], s_[2*kc+1][1]);
                a[3] = f22h2(s_[2*kc+1][2], s_[2*kc+1][3]);
                uint32_t rowaddr = sv_base + (uint32_t)((kc*16 + (lane & 15)) * SVS) * 2u;
#pragma unroll
                for (int j = 0; j < 16; j++) {
                    uint32_t b0, b1;
                    ldsm_x2_trans(b0, b1, rowaddr + j * 16);
                    uint32_t bfr[2] = {b0, b1};
                    mma_fp16(o[j], a, bfr);
                }
            }
        }

        float inv0 = 1.f / l0, inv1 = 1.f / l1;
        if (sp == 0) {
#pragma unroll
            for (int j = 0; j < 16; j++) {
                int col = j*8 + tig*2;
                *(float2*)&sO[rl0 * SO_STR + col] = make_float2(o[j][0]*inv0, o[j][1]*inv0);
                *(float2*)&sO[rl1 * SO_STR + col] = make_float2(o[j][2]*inv1, o[j][3]*inv1);
            }
        } else {
            float sum0 = 0.f, sum1 = 0.f, sq0 = 0.f, sq1 = 0.f;
#pragma unroll
            for (int j = 0; j < 16; j++) {
                int col = j*8 + tig*2;
                float2 p0 = *(float2*)&sO[rl0 * SO_STR + col];
                float2 p1 = *(float2*)&sO[rl1 * SO_STR + col];
                float v0x = p0.x - lam * (o[j][0]*inv0);
                float v0y = p0.y - lam * (o[j][1]*inv0);
                float v1x = p1.x - lam * (o[j][2]*inv1);
                float v1y = p1.y - lam * (o[j][3]*inv1);
                o[j][0] = v0x; o[j][1] = v0y; o[j][2] = v1x; o[j][3] = v1y;
                sum0 += v0x + v0y;  sq0 += v0x*v0x + v0y*v0y;
                sum1 += v1x + v1y;  sq1 += v1x*v1x + v1y*v1y;
            }
            sum0 += __shfl_xor_sync(0xffffffffu, sum0, 1);
            sum0 += __shfl_xor_sync(0xffffffffu, sum0, 2);
            sq0  += __shfl_xor_sync(0xffffffffu, sq0, 1);
            sq0  += __shfl_xor_sync(0xffffffffu, sq0, 2);
            sum1 += __shfl_xor_sync(0xffffffffu, sum1, 1);
            sum1 += __shfl_xor_sync(0xffffffffu, sum1, 2);
            sq1  += __shfl_xor_sync(0xffffffffu, sq1, 1);
            sq1  += __shfl_xor_sync(0xffffffffu, sq1, 2);
            float mu0 = sum0 * (1.0f/128.0f);
            float mu1 = sum1 * (1.0f/128.0f);
            float rstd0 = rsqrtf(sq0 * (1.0f/128.0f) - mu0*mu0 + EPS);
            float rstd1 = rsqrtf(sq1 * (1.0f/128.0f) - mu1*mu1 + EPS);
            size_t grow0 = base + q0 + rl0;
            size_t grow1 = base + q0 + rl1;
#pragma unroll
            for (int j = 0; j < 16; j++) {
                int col = j*8 + tig*2;
                float lw0 = lnw[col], lw1 = lnw[col+1];
                float lb0 = lnb[col], lb1 = lnb[col+1];
                float y0x = ((o[j][0] - mu0) * rstd0 * lw0 + lb0) * OUT_SCALE;
                float y0y = ((o[j][1] - mu0) * rstd0 * lw1 + lb1) * OUT_SCALE;
                float y1x = ((o[j][2] - mu1) * rstd1 * lw0 + lb0) * OUT_SCALE;
                float y1y = ((o[j][3] - mu1) * rstd1 * lw1 + lb1) * OUT_SCALE;
                *(__half2*)&att[grow0 * (2*CC) + vcol + col] = __floats2half2_rn(y0x, y0y);
                *(__half2*)&att[grow1 * (2*CC) + vcol + col] = __floats2half2_rn(y1x, y1y);
            }
        }
    }
}

// ================= launch =================
extern "C" void kernel_launch(void* const* d_in, const int* in_sizes, int n_in,
                              void* d_out, int out_size)
{
    const float* x    = (const float*)d_in[0];
    const float* n1w  = (const float*)d_in[1];
    const float* n1b  = (const float*)d_in[2];
    const float* wq   = (const float*)d_in[3];
    const float* wk   = (const float*)d_in[4];
    const float* wv   = (const float*)d_in[5];
    const float* lam  = (const float*)d_in[6];
    const float* alnw = (const float*)d_in[7];
    const float* alnb = (const float*)d_in[8];
    const float* pw   = (const float*)d_in[9];
    const float* pb   = (const float*)d_in[10];
    const float* n2w  = (const float*)d_in[11];
    const float* n2b  = (const float*)d_in[12];
    const float* f1w  = (const float*)d_in[13];
    const float* f1b  = (const float*)d_in[14];
    const float* f2w  = (const float*)d_in[15];
    const float* f2b  = (const float*)d_in[16];
    float* out = (float*)d_out;

    __half *xn, *q, *k, *v, *att, *xn2, *hb;
    float *xmid;
    __half *cwq, *cwk, *cwv, *cpw, *cf1, *cf2;
    cudaGetSymbolAddress((void**)&xn,   g_xn);
    cudaGetSymbolAddress((void**)&q,    g_q);
    cudaGetSymbolAddress((void**)&k,    g_k);
    cudaGetSymbolAddress((void**)&v,    g_v);
    cudaGetSymbolAddress((void**)&att,  g_att);
    cudaGetSymbolAddress((void**)&xmid, g_xmid);
    cudaGetSymbolAddress((void**)&xn2,  g_xn2);
    cudaGetSymbolAddress((void**)&hb,   g_h);
    cudaGetSymbolAddress((void**)&cwq,  g_wq);
    cudaGetSymbolAddress((void**)&cwk,  g_wk);
    cudaGetSymbolAddress((void**)&cwv,  g_wv);
    cudaGetSymbolAddress((void**)&cpw,  g_pw);
    cudaGetSymbolAddress((void**)&cf1,  g_f1);
    cudaGetSymbolAddress((void**)&cf2,  g_f2);

    cudaFuncSetAttribute(attn_mma_kernel,
                         cudaFuncAttributeMaxDynamicSharedMemorySize, ATT_SMEM);
    cudaFuncSetAttribute(qkv_gemm,
                         cudaFuncAttributeMaxDynamicSharedMemorySize, GEMM_SMEM(128));
    cudaFuncSetAttribute(tc_gemm<1, 64>,
                         cudaFuncAttributeMaxDynamicSharedMemorySize, GEMM_SMEM(64));
    cudaFuncSetAttribute(tc_gemm<2, 128>,
                         cudaFuncAttributeMaxDynamicSharedMemorySize, GEMM_SMEM(128));

    // 0. merged weight fp16 pre-conversion (one launch)
    {
        int n4a = (2*CC*CC)/4;   // 294912
        int n4b = (4*CC*CC)/4;   // 589824
        cvtw_all_kernel<<<dim3((n4b+255)/256, 6), 256>>>(
            wq, cwq, n4a,  wk, cwk, n4a,  wv, cwv, n4a,
            pw, cpw, n4a,  f1w, cf1, n4b, f2w, cf2, n4b);
    }
    // 1. LN1 (fp16 output)
    ln_kernel<<<MROWS, 256>>>(x, n1w, n1b, xn);
    // 2. merged QKV GEMM (fp16), one launch
    qkv_gemm<<<dim3(1536/128, MROWS/128, 3), 256, GEMM_SMEM(128)>>>(xn, cwq, cwk, cwv, q, k, v);
    // 3. fused differential flash attention + combine + head-LN
    attn_mma_kernel<<<dim3(NN/128, HH, BB), 256, ATT_SMEM>>>(q, k, v, lam, alnw, alnb, att);
    // 4. proj + bias + residual (64-row tiles: 384 CTAs, better wave fill)
    tc_gemm<1, 64><<<dim3(768/128, MROWS/64), 256, GEMM_SMEM(64)>>>(att, cpw, pb, x, xmid, MROWS, 768, 1536);
    // 5. LN2 (fp16 output)
    ln_kernel<<<MROWS, 256>>>(xmid, n2w, n2b, xn2);
    // 6. fc1 + bias + GELU (fp16 out)
    tc_gemm<2, 128><<<dim3(3072/128, MROWS/128), 256, GEMM_SMEM(128)>>>(xn2, cf1, f1b, nullptr, hb, MROWS, 3072, 768);
    // 7. fc2 + bias + residual (64-row tiles)
    tc_gemm<1, 64><<<dim3(768/128, MROWS/64), 256, GEMM_SMEM(64)>>>(hb, cf2, f2b, xmid, out, MROWS, 768, 3072);
}